// round 2
// baseline (speedup 1.0000x reference)
#include <cuda_runtime.h>
#include <math.h>

#define BB 2
#define TT 2048
#define HH 12
#define DD 64
#define CC 768
#define NQKV 2304
#define NEG (-1e30f)

// ---------------- scratch (device globals; no allocations allowed) ----------
__device__ float g_Wqkv[CC * NQKV];                 // packed [K=768][N=2304]
__device__ float g_QKV[3 * BB * HH * TT * DD];      // [which][b][h][t][d]
__device__ float g_O[BB * TT * CC];                 // [b*T + t][h*64 + d]
__device__ float g_cos[TT * 32];
__device__ float g_sin[TT * 32];

// ---------------- kernel 0a: pack QKV weights into one B matrix -------------
__global__ void pack_w_k(const float* __restrict__ wq,
                         const float* __restrict__ wk,
                         const float* __restrict__ wv) {
    int idx = blockIdx.x * 256 + threadIdx.x;
    if (idx >= CC * NQKV) return;
    int c = idx / NQKV, n = idx - c * NQKV;
    int which = n / 768, hd = n - which * 768;
    int h = hd >> 6, d = hd & 63;
    const float* w = (which == 0) ? wq : (which == 1) ? wk : wv;
    g_Wqkv[idx] = w[(h * CC + c) * DD + d];
}

// ---------------- kernel 0b: rope cos/sin table -----------------------------
__global__ void rope_table_k() {
    int idx = blockIdx.x * 256 + threadIdx.x;
    if (idx >= TT * 32) return;
    int t = idx >> 5, i = idx & 31;
    // inv_freq = 10000^(-2i/64) = exp2(-i * log2(10000)/32); double for accuracy,
    // rounded to fp32 like the reference, then fp32 angle multiply.
    double e = (double)i * 0.41524101186092028;   // log2(10000)/32
    float inv = exp2f((float)(-e));
    float ang = (float)t * inv;
    float s, c;
    sincosf(ang, &s, &c);
    g_cos[idx] = c;
    g_sin[idx] = s;
}

// ---------------- kernel 1: QKV GEMM + bias + RoPE --------------------------
// M=4096 (b,t), K=768, N=2304.  Tile 64x64x16, 256 threads, 4x4 microtile.
__global__ __launch_bounds__(256) void qkv_rope_k(
        const float* __restrict__ x,
        const float* __restrict__ bq,
        const float* __restrict__ bk,
        const float* __restrict__ bv) {
    __shared__ float As[16][64];   // [k][m]
    __shared__ float Bs[16][64];   // [k][n]
    const int tid = threadIdx.x;
    const int m0 = blockIdx.y * 64;
    const int n0 = blockIdx.x * 64;
    const int ty = tid >> 4, tx = tid & 15;
    const int lar = tid >> 2, lac = (tid & 3) << 2;   // A load: row, k-offset
    const int lbr = tid >> 4, lbc = (tid & 15) << 2;  // B load: k-row, n-offset
    float acc[4][4] = {};

    for (int k0 = 0; k0 < CC; k0 += 16) {
        float4 a4 = *(const float4*)&x[(m0 + lar) * CC + k0 + lac];
        float4 b4 = *(const float4*)&g_Wqkv[(k0 + lbr) * NQKV + n0 + lbc];
        __syncthreads();
        As[lac + 0][lar] = a4.x;
        As[lac + 1][lar] = a4.y;
        As[lac + 2][lar] = a4.z;
        As[lac + 3][lar] = a4.w;
        *(float4*)&Bs[lbr][lbc] = b4;
        __syncthreads();
#pragma unroll
        for (int k = 0; k < 16; k++) {
            float4 av = *(float4*)&As[k][ty << 2];
            float4 bv2 = *(float4*)&Bs[k][tx << 2];
            float a[4] = {av.x, av.y, av.z, av.w};
            float b[4] = {bv2.x, bv2.y, bv2.z, bv2.w};
#pragma unroll
            for (int i = 0; i < 4; i++)
#pragma unroll
                for (int j = 0; j < 4; j++)
                    acc[i][j] = fmaf(a[i], b[j], acc[i][j]);
        }
    }

    const int which = n0 / 768;
    const int h = (n0 % 768) >> 6;
    const int d0 = tx << 2;
    const float* bias = (which == 0) ? bq : (which == 1) ? bk : bv;
    float bias4[4];
#pragma unroll
    for (int j = 0; j < 4; j++) bias4[j] = bias[h * 64 + d0 + j];

#pragma unroll
    for (int i = 0; i < 4; i++) {
        int m = m0 + (ty << 2) + i;
        int b = m >> 11, t = m & 2047;
        float v[4];
#pragma unroll
        for (int j = 0; j < 4; j++) v[j] = acc[i][j] + bias4[j];
        if (which < 2) {
#pragma unroll
            for (int p = 0; p < 2; p++) {
                int ii = (d0 >> 1) + p;           // rope pair index 0..31
                float c = g_cos[t * 32 + ii];
                float s = g_sin[t * 32 + ii];
                float xr = v[2 * p], xi = v[2 * p + 1];
                v[2 * p]     = xr * c - xi * s;
                v[2 * p + 1] = xr * s + xi * c;
            }
        }
        float* dst = &g_QKV[(((which * BB + b) * HH + h) * TT + t) * DD + d0];
        *(float4*)dst = make_float4(v[0], v[1], v[2], v[3]);
    }
}

// ---------------- kernel 2: causal flash attention --------------------------
// Block = one 64-row query tile of one (b,h). 256 threads.
// smem: Qt[d][r] 64x64, Kt[d][c] 64x64, Vs[c][d] 64x64, Ss[r][c] 64x(stride 68)
#define SS_STRIDE 68
#define ATTN_SMEM_FLOATS (3 * 64 * 64 + 64 * SS_STRIDE)
#define ATTN_SMEM_BYTES (ATTN_SMEM_FLOATS * 4)

__global__ __launch_bounds__(256) void attn_k() {
    extern __shared__ float sm[];
    float* Qt = sm;
    float* Kt = sm + 64 * 64;
    float* Vs = sm + 2 * 64 * 64;
    float* Ss = sm + 3 * 64 * 64;
    __shared__ float mrow[64], lrow[64], arow[64];

    const int tid = threadIdx.x;
    const int qi = (int)gridDim.x - 1 - (int)blockIdx.x;  // heavy tiles first
    const int bh = blockIdx.y;
    const int b = bh / HH, h = bh % HH;
    const int q0 = qi * 64;

    const float* Qg = g_QKV + ((0 * BB + b) * HH + h) * TT * DD;
    const float* Kg = g_QKV + ((1 * BB + b) * HH + h) * TT * DD;
    const float* Vg = g_QKV + ((2 * BB + b) * HH + h) * TT * DD;

    const int ty = tid >> 4, tx = tid & 15;
    const int ty4 = ty << 2, tx4 = tx << 2;
    const int lr = tid >> 2;            // 0..63 (row for tile loads)
    const int ldb = (tid & 3) << 4;     // 0,16,32,48 (d block)

    // load Q tile transposed, fold 1/sqrt(64) = 0.125 scale
#pragma unroll
    for (int kk = 0; kk < 16; kk += 4) {
        float4 qv = *(const float4*)&Qg[(q0 + lr) * 64 + ldb + kk];
        Qt[(ldb + kk + 0) * 64 + lr] = qv.x * 0.125f;
        Qt[(ldb + kk + 1) * 64 + lr] = qv.y * 0.125f;
        Qt[(ldb + kk + 2) * 64 + lr] = qv.z * 0.125f;
        Qt[(ldb + kk + 3) * 64 + lr] = qv.w * 0.125f;
    }
    if (tid < 64) { mrow[tid] = NEG; lrow[tid] = 0.0f; }

    float acco[4][4] = {};

    for (int j = 0; j <= qi; j++) {
        __syncthreads();  // guard smem reuse + Qt/stats visibility on first iter
        // load K (transposed) and V tiles
#pragma unroll
        for (int kk = 0; kk < 16; kk += 4) {
            float4 kv = *(const float4*)&Kg[(j * 64 + lr) * 64 + ldb + kk];
            Kt[(ldb + kk + 0) * 64 + lr] = kv.x;
            Kt[(ldb + kk + 1) * 64 + lr] = kv.y;
            Kt[(ldb + kk + 2) * 64 + lr] = kv.z;
            Kt[(ldb + kk + 3) * 64 + lr] = kv.w;
            float4 vv = *(const float4*)&Vg[(j * 64 + lr) * 64 + ldb + kk];
            *(float4*)&Vs[lr * 64 + ldb + kk] = vv;
        }
        __syncthreads();

        // S = Q * K^T  (4x4 per thread)
        float accs[4][4] = {};
#pragma unroll 16
        for (int dd = 0; dd < 64; dd++) {
            float4 aq = *(float4*)&Qt[dd * 64 + ty4];
            float4 bk = *(float4*)&Kt[dd * 64 + tx4];
            float a[4] = {aq.x, aq.y, aq.z, aq.w};
            float c[4] = {bk.x, bk.y, bk.z, bk.w};
#pragma unroll
            for (int i = 0; i < 4; i++)
#pragma unroll
                for (int jj = 0; jj < 4; jj++)
                    accs[i][jj] = fmaf(a[i], c[jj], accs[i][jj]);
        }

        // causal mask (only diagonal tile) + write to Ss
        const bool diag = (j == qi);
#pragma unroll
        for (int i = 0; i < 4; i++) {
            int gr = ty4 + i;                 // local row == global offset match
            float v[4];
#pragma unroll
            for (int jj = 0; jj < 4; jj++) {
                v[jj] = accs[i][jj];
                if (diag && (tx4 + jj > gr)) v[jj] = NEG;
            }
            *(float4*)&Ss[(ty4 + i) * SS_STRIDE + tx4] =
                make_float4(v[0], v[1], v[2], v[3]);
        }
        __syncthreads();

        // online softmax: 4 threads per row
        {
            int row = tid >> 2, q = tid & 3;
            float* srow = &Ss[row * SS_STRIDE + q * 16];
            float mx = NEG;
#pragma unroll
            for (int k = 0; k < 16; k++) mx = fmaxf(mx, srow[k]);
            mx = fmaxf(mx, __shfl_xor_sync(0xffffffffu, mx, 1));
            mx = fmaxf(mx, __shfl_xor_sync(0xffffffffu, mx, 2));
            float mold = mrow[row];
            float mnew = fmaxf(mold, mx);
            float sum = 0.0f;
#pragma unroll
            for (int k = 0; k < 16; k++) {
                float p = __expf(srow[k] - mnew);
                srow[k] = p;
                sum += p;
            }
            sum += __shfl_xor_sync(0xffffffffu, sum, 1);
            sum += __shfl_xor_sync(0xffffffffu, sum, 2);
            if (q == 0) {
                float al = __expf(mold - mnew);
                arow[row] = al;
                lrow[row] = lrow[row] * al + sum;
                mrow[row] = mnew;
            }
        }
        __syncthreads();

        // rescale O, then O += P * V
        float al[4];
#pragma unroll
        for (int i = 0; i < 4; i++) al[i] = arow[ty4 + i];
#pragma unroll
        for (int i = 0; i < 4; i++)
#pragma unroll
            for (int jj = 0; jj < 4; jj++) acco[i][jj] *= al[i];

#pragma unroll 8
        for (int cc = 0; cc < 64; cc++) {
            float p[4];
#pragma unroll
            for (int i = 0; i < 4; i++) p[i] = Ss[(ty4 + i) * SS_STRIDE + cc];
            float4 vv = *(float4*)&Vs[cc * 64 + tx4];
            float v[4] = {vv.x, vv.y, vv.z, vv.w};
#pragma unroll
            for (int i = 0; i < 4; i++)
#pragma unroll
                for (int jj = 0; jj < 4; jj++)
                    acco[i][jj] = fmaf(p[i], v[jj], acco[i][jj]);
        }
    }

    // final normalize + store to g_O [b*T+t][h*64+d]
    float linv[4];
#pragma unroll
    for (int i = 0; i < 4; i++) linv[i] = 1.0f / lrow[ty4 + i];
#pragma unroll
    for (int i = 0; i < 4; i++) {
        int t = q0 + ty4 + i;
        float* dst = &g_O[(b * TT + t) * CC + h * 64 + tx4];
        *(float4*)dst = make_float4(acco[i][0] * linv[i], acco[i][1] * linv[i],
                                    acco[i][2] * linv[i], acco[i][3] * linv[i]);
    }
}

// ---------------- kernel 3: output projection -------------------------------
// out[m,n] = sum_k g_O[m,k] * W_O[k,n] + b_O[n];  M=4096, K=768, N=768
__global__ __launch_bounds__(256) void out_proj_k(
        const float* __restrict__ wo,
        const float* __restrict__ bo,
        float* __restrict__ out) {
    __shared__ float As[16][64];
    __shared__ float Bs[16][64];
    const int tid = threadIdx.x;
    const int m0 = blockIdx.y * 64;
    const int n0 = blockIdx.x * 64;
    const int ty = tid >> 4, tx = tid & 15;
    const int lar = tid >> 2, lac = (tid & 3) << 2;
    const int lbr = tid >> 4, lbc = (tid & 15) << 2;
    float acc[4][4] = {};

    for (int k0 = 0; k0 < CC; k0 += 16) {
        float4 a4 = *(const float4*)&g_O[(m0 + lar) * CC + k0 + lac];
        float4 b4 = *(const float4*)&wo[(k0 + lbr) * CC + n0 + lbc];
        __syncthreads();
        As[lac + 0][lar] = a4.x;
        As[lac + 1][lar] = a4.y;
        As[lac + 2][lar] = a4.z;
        As[lac + 3][lar] = a4.w;
        *(float4*)&Bs[lbr][lbc] = b4;
        __syncthreads();
#pragma unroll
        for (int k = 0; k < 16; k++) {
            float4 av = *(float4*)&As[k][ty << 2];
            float4 bv2 = *(float4*)&Bs[k][tx << 2];
            float a[4] = {av.x, av.y, av.z, av.w};
            float b[4] = {bv2.x, bv2.y, bv2.z, bv2.w};
#pragma unroll
            for (int i = 0; i < 4; i++)
#pragma unroll
                for (int j = 0; j < 4; j++)
                    acc[i][j] = fmaf(a[i], b[j], acc[i][j]);
        }
    }

    float bias4[4];
#pragma unroll
    for (int j = 0; j < 4; j++) bias4[j] = bo[n0 + (tx << 2) + j];
#pragma unroll
    for (int i = 0; i < 4; i++) {
        int m = m0 + (ty << 2) + i;
        float* dst = &out[m * CC + n0 + (tx << 2)];
        *(float4*)dst = make_float4(acc[i][0] + bias4[0], acc[i][1] + bias4[1],
                                    acc[i][2] + bias4[2], acc[i][3] + bias4[3]);
    }
}

// ---------------- launcher ---------------------------------------------------
extern "C" void kernel_launch(void* const* d_in, const int* in_sizes, int n_in,
                              void* d_out, int out_size) {
    const float* x  = (const float*)d_in[0];
    const float* wq = (const float*)d_in[1];
    const float* bq = (const float*)d_in[2];
    const float* wk = (const float*)d_in[3];
    const float* bk = (const float*)d_in[4];
    const float* wv = (const float*)d_in[5];
    const float* bv = (const float*)d_in[6];
    const float* wo = (const float*)d_in[7];
    const float* bo = (const float*)d_in[8];
    float* out = (float*)d_out;

    static int attn_attr_set = 0;
    (void)attn_attr_set;
    cudaFuncSetAttribute(attn_k, cudaFuncAttributeMaxDynamicSharedMemorySize,
                         ATTN_SMEM_BYTES);

    pack_w_k<<<(CC * NQKV + 255) / 256, 256>>>(wq, wk, wv);
    rope_table_k<<<(TT * 32 + 255) / 256, 256>>>();
    qkv_rope_k<<<dim3(NQKV / 64, (BB * TT) / 64), 256>>>(x, bq, bk, bv);
    attn_k<<<dim3(TT / 64, BB * HH), 256, ATTN_SMEM_BYTES>>>();
    out_proj_k<<<dim3(CC / 64, (BB * TT) / 64), 256>>>(wo, bo, out);
}

// round 4
// speedup vs baseline: 1.1746x; 1.1746x over previous
#include <cuda_runtime.h>
#include <math.h>

#define BB 2
#define TT 2048
#define HH 12
#define DD 64
#define CC 768
#define NQKV 2304
#define NEG (-1e30f)

// ---------------- scratch (device globals; no allocations allowed) ----------
__device__ float g_Wqkv[CC * NQKV];                 // packed [K=768][N=2304]
__device__ float g_QKV[3 * BB * HH * TT * DD];      // [which][b][h][t][d]
__device__ float g_O[BB * TT * CC];                 // [b*T + t][h*64 + d]
__device__ float g_cos[TT * 32];
__device__ float g_sin[TT * 32];

// ---------------- kernel 0a: pack QKV weights into one B matrix -------------
__global__ void pack_w_k(const float* __restrict__ wq,
                         const float* __restrict__ wk,
                         const float* __restrict__ wv) {
    int idx = blockIdx.x * 256 + threadIdx.x;
    if (idx >= CC * NQKV) return;
    int c = idx / NQKV, n = idx - c * NQKV;
    int which = n / 768, hd = n - which * 768;
    int h = hd >> 6, d = hd & 63;
    const float* w = (which == 0) ? wq : (which == 1) ? wk : wv;
    g_Wqkv[idx] = w[(h * CC + c) * DD + d];
}

// ---------------- kernel 0b: rope cos/sin table -----------------------------
__global__ void rope_table_k() {
    int idx = blockIdx.x * 256 + threadIdx.x;
    if (idx >= TT * 32) return;
    int t = idx >> 5, i = idx & 31;
    double e = (double)i * 0.41524101186092028;   // log2(10000)/32
    float inv = exp2f((float)(-e));
    float ang = (float)t * inv;
    float s, c;
    sincosf(ang, &s, &c);
    g_cos[idx] = c;
    g_sin[idx] = s;
}

// ---------------- kernel 1: QKV GEMM + bias + RoPE --------------------------
// M=4096, K=768, N=2304. Tile 128x64x16, 256 threads, 8x4 microtile.
__global__ __launch_bounds__(256) void qkv_rope_k(
        const float* __restrict__ x,
        const float* __restrict__ bq,
        const float* __restrict__ bk,
        const float* __restrict__ bv) {
    __shared__ float As[16 * 128];   // k-major, swizzled: [k][r ^ ((k>>3)<<4)]
    __shared__ float Bs[16 * 64];    // [k][n]
    const int tid = threadIdx.x;
    const int m0 = blockIdx.y * 128;
    const int n0 = blockIdx.x * 64;
    const int ty = tid >> 4, tx = tid & 15;
    const int row0 = ty << 3, col0 = tx << 2;
    const int lr = tid >> 1, lkb = (tid & 1) << 3;   // A: row, k-base (0|8)
    const int lbk = tid >> 4, lbn = (tid & 15) << 2; // B: k-row, n-offset
    float acc[8][4] = {};

    for (int k0 = 0; k0 < CC; k0 += 16) {
        float4 a0 = *(const float4*)&x[(m0 + lr) * CC + k0 + lkb];
        float4 a1 = *(const float4*)&x[(m0 + lr) * CC + k0 + lkb + 4];
        float4 b0 = *(const float4*)&g_Wqkv[(k0 + lbk) * NQKV + n0 + lbn];
        __syncthreads();
        {
            int xr = lr ^ ((lkb >> 3) << 4);
            As[(lkb + 0) * 128 + xr] = a0.x;
            As[(lkb + 1) * 128 + xr] = a0.y;
            As[(lkb + 2) * 128 + xr] = a0.z;
            As[(lkb + 3) * 128 + xr] = a0.w;
            As[(lkb + 4) * 128 + xr] = a1.x;
            As[(lkb + 5) * 128 + xr] = a1.y;
            As[(lkb + 6) * 128 + xr] = a1.z;
            As[(lkb + 7) * 128 + xr] = a1.w;
        }
        *(float4*)&Bs[lbk * 64 + lbn] = b0;
        __syncthreads();
#pragma unroll
        for (int k = 0; k < 16; k++) {
            int rb = row0 ^ ((k >> 3) << 4);
            float4 av0 = *(float4*)&As[k * 128 + rb];
            float4 av1 = *(float4*)&As[k * 128 + rb + 4];
            float4 bv4 = *(float4*)&Bs[k * 64 + col0];
            float a[8] = {av0.x, av0.y, av0.z, av0.w, av1.x, av1.y, av1.z, av1.w};
            float b[4] = {bv4.x, bv4.y, bv4.z, bv4.w};
#pragma unroll
            for (int i = 0; i < 8; i++)
#pragma unroll
                for (int j = 0; j < 4; j++)
                    acc[i][j] = fmaf(a[i], b[j], acc[i][j]);
        }
    }

    const int which = n0 / 768;
    const int h = (n0 % 768) >> 6;
    const float* bias = (which == 0) ? bq : (which == 1) ? bk : bv;
    float bias4[4];
#pragma unroll
    for (int j = 0; j < 4; j++) bias4[j] = bias[h * 64 + col0 + j];

#pragma unroll
    for (int i = 0; i < 8; i++) {
        int m = m0 + row0 + i;
        int b = m >> 11, t = m & 2047;
        float v[4];
#pragma unroll
        for (int j = 0; j < 4; j++) v[j] = acc[i][j] + bias4[j];
        if (which < 2) {
#pragma unroll
            for (int p = 0; p < 2; p++) {
                int ii = (col0 >> 1) + p;
                float c = g_cos[t * 32 + ii];
                float s = g_sin[t * 32 + ii];
                float xr = v[2 * p], xi = v[2 * p + 1];
                v[2 * p]     = xr * c - xi * s;
                v[2 * p + 1] = xr * s + xi * c;
            }
        }
        float* dst = &g_QKV[(((which * BB + b) * HH + h) * TT + t) * DD + col0];
        *(float4*)dst = make_float4(v[0], v[1], v[2], v[3]);
    }
}

// ---------------- kernel 2: causal flash attention --------------------------
// Block = 128-query tile of one (b,h). 256 threads, 8x4 microtile.
// smem: Qt[64][128] (swz), Kt[64][64] (swz), Vs[64][64], Pt[64][128] (chunk-swz)
#define ATTN_SMEM_FLOATS (64 * 128 + 64 * 64 + 64 * 64 + 64 * 128)
#define ATTN_SMEM_BYTES (ATTN_SMEM_FLOATS * 4)

__global__ __launch_bounds__(256, 2) void attn_k() {
    extern __shared__ float sm[];
    float* Qt = sm;                     // 8192
    float* Kt = sm + 64 * 128;          // 4096
    float* Vs = Kt + 64 * 64;           // 4096
    float* Pt = Vs + 64 * 64;           // 8192

    const int tid = threadIdx.x;
    const int qi = (int)gridDim.x - 1 - (int)blockIdx.x;  // heavy tiles first
    const int bh = blockIdx.y;
    const int b = bh / HH, h = bh % HH;
    const int q0 = qi * 128;

    const float* Qg = g_QKV + ((0 * BB + b) * HH + h) * TT * DD;
    const float* Kg = g_QKV + ((1 * BB + b) * HH + h) * TT * DD;
    const float* Vg = g_QKV + ((2 * BB + b) * HH + h) * TT * DD;

    const int ty = tid >> 4, tx = tid & 15;
    const int row0 = ty << 3, col0 = tx << 2;

    // load Q tile transposed (swizzled), fold 1/8 scale
    {
        int r = tid >> 1;
        int dblk = (tid & 1) << 5;      // 0 or 32
        const float* src = &Qg[(q0 + r) * DD + dblk];
#pragma unroll
        for (int q = 0; q < 8; q++) {
            float4 v = *(const float4*)&src[q * 4];
            int d = dblk + q * 4;
            float vals[4] = {v.x, v.y, v.z, v.w};
#pragma unroll
            for (int e = 0; e < 4; e++) {
                int dd = d + e;
                Qt[dd * 128 + (r ^ ((dd >> 5) << 4))] = vals[e] * 0.125f;
            }
        }
    }

    float m_[8], l_[8];
#pragma unroll
    for (int i = 0; i < 8; i++) { m_[i] = NEG; l_[i] = 0.0f; }
    float acco[8][4] = {};

    const int njt = 2 * qi + 2;
    for (int j = 0; j < njt; j++) {
        __syncthreads();   // prev PV done before K/V overwrite (also Qt on j=0)
        {
            int c = tid >> 2;
            int dblk = (tid & 3) << 4;  // 0,16,32,48
            const float* ksrc = &Kg[(j * 64 + c) * DD + dblk];
            const float* vsrc = &Vg[(j * 64 + c) * DD + dblk];
#pragma unroll
            for (int q = 0; q < 4; q++) {
                float4 kv = *(const float4*)&ksrc[q * 4];
                float kvals[4] = {kv.x, kv.y, kv.z, kv.w};
#pragma unroll
                for (int e = 0; e < 4; e++) {
                    int dd = dblk + q * 4 + e;
                    Kt[dd * 64 + (c ^ (((dd >> 4) & 3) << 3))] = kvals[e];
                }
                *(float4*)&Vs[c * 64 + dblk + q * 4] = *(const float4*)&vsrc[q * 4];
            }
        }
        __syncthreads();

        // S^T: accs[col][row], 4x8 per thread
        float accs[4][8] = {};
#pragma unroll 8
        for (int dd = 0; dd < 64; dd++) {
            int rb = row0 ^ ((dd >> 5) << 4);
            float4 a0 = *(float4*)&Qt[dd * 128 + rb];
            float4 a1 = *(float4*)&Qt[dd * 128 + rb + 4];
            float4 bb = *(float4*)&Kt[dd * 64 + (col0 ^ (((dd >> 4) & 3) << 3))];
            float a[8] = {a0.x, a0.y, a0.z, a0.w, a1.x, a1.y, a1.z, a1.w};
            float bv[4] = {bb.x, bb.y, bb.z, bb.w};
#pragma unroll
            for (int jj = 0; jj < 4; jj++)
#pragma unroll
                for (int i = 0; i < 8; i++)
                    accs[jj][i] = fmaf(bv[jj], a[i], accs[jj][i]);
        }

        // causal mask: only the last two k-tiles intersect the diagonal
        if (j >= njt - 2) {
#pragma unroll
            for (int jj = 0; jj < 4; jj++) {
                int c = j * 64 + col0 + jj;
#pragma unroll
                for (int i = 0; i < 8; i++) {
                    int r = q0 + row0 + i;
                    if (c > r) accs[jj][i] = NEG;
                }
            }
        }

        // register-resident online softmax (reduce across 16 tx lanes)
        float alpha[8], rs[8];
#pragma unroll
        for (int i = 0; i < 8; i++) {
            float mm = fmaxf(fmaxf(accs[0][i], accs[1][i]),
                             fmaxf(accs[2][i], accs[3][i]));
            mm = fmaxf(mm, __shfl_xor_sync(0xffffffffu, mm, 1));
            mm = fmaxf(mm, __shfl_xor_sync(0xffffffffu, mm, 2));
            mm = fmaxf(mm, __shfl_xor_sync(0xffffffffu, mm, 4));
            mm = fmaxf(mm, __shfl_xor_sync(0xffffffffu, mm, 8));
            float mnew = fmaxf(m_[i], mm);
            alpha[i] = __expf(m_[i] - mnew);
            m_[i] = mnew;
            float s0 = 0.0f;
#pragma unroll
            for (int jj = 0; jj < 4; jj++) {
                float p = __expf(accs[jj][i] - mnew);
                accs[jj][i] = p;
                s0 += p;
            }
            rs[i] = s0;
        }
#pragma unroll
        for (int i = 0; i < 8; i++) {
            rs[i] += __shfl_xor_sync(0xffffffffu, rs[i], 1);
            rs[i] += __shfl_xor_sync(0xffffffffu, rs[i], 2);
            rs[i] += __shfl_xor_sync(0xffffffffu, rs[i], 4);
            rs[i] += __shfl_xor_sync(0xffffffffu, rs[i], 8);
            l_[i] = l_[i] * alpha[i] + rs[i];
#pragma unroll
            for (int jc = 0; jc < 4; jc++) acco[i][jc] *= alpha[i];
        }

        // store P^T with chunk-XOR swizzle (conflict-free, float4)
        {
            int ch = row0 >> 2;          // 2*ty
            int s = tx & 7;
#pragma unroll
            for (int jj = 0; jj < 4; jj++) {
                int c = col0 + jj;
                *(float4*)&Pt[c * 128 + ((ch ^ s) << 2)] =
                    make_float4(accs[jj][0], accs[jj][1], accs[jj][2], accs[jj][3]);
                *(float4*)&Pt[c * 128 + (((ch + 1) ^ s) << 2)] =
                    make_float4(accs[jj][4], accs[jj][5], accs[jj][6], accs[jj][7]);
            }
        }
        __syncthreads();

        // O += P * V
#pragma unroll 8
        for (int cc = 0; cc < 64; cc++) {
            int s = (cc >> 2) & 7;
            int ch = row0 >> 2;
            float4 p0 = *(float4*)&Pt[cc * 128 + ((ch ^ s) << 2)];
            float4 p1 = *(float4*)&Pt[cc * 128 + (((ch + 1) ^ s) << 2)];
            float4 vv = *(float4*)&Vs[cc * 64 + col0];
            float p[8] = {p0.x, p0.y, p0.z, p0.w, p1.x, p1.y, p1.z, p1.w};
            float v[4] = {vv.x, vv.y, vv.z, vv.w};
#pragma unroll
            for (int i = 0; i < 8; i++)
#pragma unroll
                for (int jc = 0; jc < 4; jc++)
                    acco[i][jc] = fmaf(p[i], v[jc], acco[i][jc]);
        }
    }

    // normalize + store
#pragma unroll
    for (int i = 0; i < 8; i++) {
        float inv = 1.0f / l_[i];
        int t = q0 + row0 + i;
        float* dst = &g_O[(b * TT + t) * CC + h * 64 + col0];
        *(float4*)dst = make_float4(acco[i][0] * inv, acco[i][1] * inv,
                                    acco[i][2] * inv, acco[i][3] * inv);
    }
}

// ---------------- kernel 3: output projection -------------------------------
// out = g_O (4096x768) * W_O (768x768) + b_O. Tile 128x64x16, 8x4 micro.
__global__ __launch_bounds__(256) void out_proj_k(
        const float* __restrict__ wo,
        const float* __restrict__ bo,
        float* __restrict__ out) {
    __shared__ float As[16 * 128];
    __shared__ float Bs[16 * 64];
    const int tid = threadIdx.x;
    const int m0 = blockIdx.y * 128;
    const int n0 = blockIdx.x * 64;
    const int ty = tid >> 4, tx = tid & 15;
    const int row0 = ty << 3, col0 = tx << 2;
    const int lr = tid >> 1, lkb = (tid & 1) << 3;
    const int lbk = tid >> 4, lbn = (tid & 15) << 2;
    float acc[8][4] = {};

    for (int k0 = 0; k0 < CC; k0 += 16) {
        float4 a0 = *(const float4*)&g_O[(m0 + lr) * CC + k0 + lkb];
        float4 a1 = *(const float4*)&g_O[(m0 + lr) * CC + k0 + lkb + 4];
        float4 b0 = *(const float4*)&wo[(k0 + lbk) * CC + n0 + lbn];
        __syncthreads();
        {
            int xr = lr ^ ((lkb >> 3) << 4);
            As[(lkb + 0) * 128 + xr] = a0.x;
            As[(lkb + 1) * 128 + xr] = a0.y;
            As[(lkb + 2) * 128 + xr] = a0.z;
            As[(lkb + 3) * 128 + xr] = a0.w;
            As[(lkb + 4) * 128 + xr] = a1.x;
            As[(lkb + 5) * 128 + xr] = a1.y;
            As[(lkb + 6) * 128 + xr] = a1.z;
            As[(lkb + 7) * 128 + xr] = a1.w;
        }
        *(float4*)&Bs[lbk * 64 + lbn] = b0;
        __syncthreads();
#pragma unroll
        for (int k = 0; k < 16; k++) {
            int rb = row0 ^ ((k >> 3) << 4);
            float4 av0 = *(float4*)&As[k * 128 + rb];
            float4 av1 = *(float4*)&As[k * 128 + rb + 4];
            float4 bv4 = *(float4*)&Bs[k * 64 + col0];
            float a[8] = {av0.x, av0.y, av0.z, av0.w, av1.x, av1.y, av1.z, av1.w};
            float b[4] = {bv4.x, bv4.y, bv4.z, bv4.w};
#pragma unroll
            for (int i = 0; i < 8; i++)
#pragma unroll
                for (int j = 0; j < 4; j++)
                    acc[i][j] = fmaf(a[i], b[j], acc[i][j]);
        }
    }

    float bias4[4];
#pragma unroll
    for (int j = 0; j < 4; j++) bias4[j] = bo[n0 + col0 + j];
#pragma unroll
    for (int i = 0; i < 8; i++) {
        int m = m0 + row0 + i;
        float* dst = &out[m * CC + n0 + col0];
        *(float4*)dst = make_float4(acc[i][0] + bias4[0], acc[i][1] + bias4[1],
                                    acc[i][2] + bias4[2], acc[i][3] + bias4[3]);
    }
}

// ---------------- launcher ---------------------------------------------------
extern "C" void kernel_launch(void* const* d_in, const int* in_sizes, int n_in,
                              void* d_out, int out_size) {
    const float* x  = (const float*)d_in[0];
    const float* wq = (const float*)d_in[1];
    const float* bq = (const float*)d_in[2];
    const float* wk = (const float*)d_in[3];
    const float* bk = (const float*)d_in[4];
    const float* wv = (const float*)d_in[5];
    const float* bv = (const float*)d_in[6];
    const float* wo = (const float*)d_in[7];
    const float* bo = (const float*)d_in[8];
    float* out = (float*)d_out;

    cudaFuncSetAttribute(attn_k, cudaFuncAttributeMaxDynamicSharedMemorySize,
                         ATTN_SMEM_BYTES);

    pack_w_k<<<(CC * NQKV + 255) / 256, 256>>>(wq, wk, wv);
    rope_table_k<<<(TT * 32 + 255) / 256, 256>>>();
    qkv_rope_k<<<dim3(NQKV / 64, (BB * TT) / 128), 256>>>(x, bq, bk, bv);
    attn_k<<<dim3(TT / 128, BB * HH), 256, ATTN_SMEM_BYTES>>>();
    out_proj_k<<<dim3(CC / 64, (BB * TT) / 128), 256>>>(wo, bo, out);
}

// round 5
// speedup vs baseline: 1.7348x; 1.4769x over previous
#include <cuda_runtime.h>
#include <math.h>

#define BB 2
#define TT 2048
#define HH 12
#define DD 64
#define CC 768
#define NQKV 2304
#define NEG (-1e30f)

// ---------------- scratch (device globals; no allocations allowed) ----------
__device__ float g_Wqkv[CC * NQKV];                 // packed [K=768][N=2304]
__device__ float g_QKV[3 * BB * HH * TT * DD];      // [which][b][h][t][d]
__device__ float g_O[BB * TT * CC];                 // [b*T + t][h*64 + d]
__device__ float g_cos[TT * 32];
__device__ float g_sin[TT * 32];

// ---------------- helpers ----------------------------------------------------
__device__ __forceinline__ unsigned f2tf(float f) {
    unsigned u;
    asm("cvt.rna.tf32.f32 %0, %1;" : "=r"(u) : "f"(f));
    return u;
}

__device__ __forceinline__ void mma_tf32(
        float& c0, float& c1, float& c2, float& c3,
        unsigned a0, unsigned a1, unsigned a2, unsigned a3,
        unsigned b0, unsigned b1) {
    asm("mma.sync.aligned.m16n8k8.row.col.f32.tf32.tf32.f32 "
        "{%0,%1,%2,%3}, {%4,%5,%6,%7}, {%8,%9}, {%0,%1,%2,%3};"
        : "+f"(c0), "+f"(c1), "+f"(c2), "+f"(c3)
        : "r"(a0), "r"(a1), "r"(a2), "r"(a3), "r"(b0), "r"(b1));
}

// ---------------- kernel 0a: pack QKV weights into one B matrix -------------
__global__ void pack_w_k(const float* __restrict__ wq,
                         const float* __restrict__ wk,
                         const float* __restrict__ wv) {
    int idx = blockIdx.x * 256 + threadIdx.x;
    if (idx >= CC * NQKV) return;
    int c = idx / NQKV, n = idx - c * NQKV;
    int which = n / 768, hd = n - which * 768;
    int h = hd >> 6, d = hd & 63;
    const float* w = (which == 0) ? wq : (which == 1) ? wk : wv;
    g_Wqkv[idx] = w[(h * CC + c) * DD + d];
}

// ---------------- kernel 0b: rope cos/sin table -----------------------------
__global__ void rope_table_k() {
    int idx = blockIdx.x * 256 + threadIdx.x;
    if (idx >= TT * 32) return;
    int t = idx >> 5, i = idx & 31;
    double e = (double)i * 0.41524101186092028;   // log2(10000)/32
    float inv = exp2f((float)(-e));
    float ang = (float)t * inv;
    float s, c;
    sincosf(ang, &s, &c);
    g_cos[idx] = c;
    g_sin[idx] = s;
}

// ---------------- kernel 1: QKV GEMM + bias + RoPE (fp32 SIMT) --------------
__global__ __launch_bounds__(256) void qkv_rope_k(
        const float* __restrict__ x,
        const float* __restrict__ bq,
        const float* __restrict__ bk,
        const float* __restrict__ bv) {
    __shared__ float As[16 * 128];
    __shared__ float Bs[16 * 64];
    const int tid = threadIdx.x;
    const int m0 = blockIdx.y * 128;
    const int n0 = blockIdx.x * 64;
    const int ty = tid >> 4, tx = tid & 15;
    const int row0 = ty << 3, col0 = tx << 2;
    const int lr = tid >> 1, lkb = (tid & 1) << 3;
    const int lbk = tid >> 4, lbn = (tid & 15) << 2;
    float acc[8][4] = {};

    for (int k0 = 0; k0 < CC; k0 += 16) {
        float4 a0 = *(const float4*)&x[(m0 + lr) * CC + k0 + lkb];
        float4 a1 = *(const float4*)&x[(m0 + lr) * CC + k0 + lkb + 4];
        float4 b0 = *(const float4*)&g_Wqkv[(k0 + lbk) * NQKV + n0 + lbn];
        __syncthreads();
        {
            int xr = lr ^ ((lkb >> 3) << 4);
            As[(lkb + 0) * 128 + xr] = a0.x;
            As[(lkb + 1) * 128 + xr] = a0.y;
            As[(lkb + 2) * 128 + xr] = a0.z;
            As[(lkb + 3) * 128 + xr] = a0.w;
            As[(lkb + 4) * 128 + xr] = a1.x;
            As[(lkb + 5) * 128 + xr] = a1.y;
            As[(lkb + 6) * 128 + xr] = a1.z;
            As[(lkb + 7) * 128 + xr] = a1.w;
        }
        *(float4*)&Bs[lbk * 64 + lbn] = b0;
        __syncthreads();
#pragma unroll
        for (int k = 0; k < 16; k++) {
            int rb = row0 ^ ((k >> 3) << 4);
            float4 av0 = *(float4*)&As[k * 128 + rb];
            float4 av1 = *(float4*)&As[k * 128 + rb + 4];
            float4 bv4 = *(float4*)&Bs[k * 64 + col0];
            float a[8] = {av0.x, av0.y, av0.z, av0.w, av1.x, av1.y, av1.z, av1.w};
            float b[4] = {bv4.x, bv4.y, bv4.z, bv4.w};
#pragma unroll
            for (int i = 0; i < 8; i++)
#pragma unroll
                for (int j = 0; j < 4; j++)
                    acc[i][j] = fmaf(a[i], b[j], acc[i][j]);
        }
    }

    const int which = n0 / 768;
    const int h = (n0 % 768) >> 6;
    const float* bias = (which == 0) ? bq : (which == 1) ? bk : bv;
    float bias4[4];
#pragma unroll
    for (int j = 0; j < 4; j++) bias4[j] = bias[h * 64 + col0 + j];

#pragma unroll
    for (int i = 0; i < 8; i++) {
        int m = m0 + row0 + i;
        int b = m >> 11, t = m & 2047;
        float v[4];
#pragma unroll
        for (int j = 0; j < 4; j++) v[j] = acc[i][j] + bias4[j];
        if (which < 2) {
#pragma unroll
            for (int p = 0; p < 2; p++) {
                int ii = (col0 >> 1) + p;
                float c = g_cos[t * 32 + ii];
                float s = g_sin[t * 32 + ii];
                float xr = v[2 * p], xi = v[2 * p + 1];
                v[2 * p]     = xr * c - xi * s;
                v[2 * p + 1] = xr * s + xi * c;
            }
        }
        float* dst = &g_QKV[(((which * BB + b) * HH + h) * TT + t) * DD + col0];
        *(float4*)dst = make_float4(v[0], v[1], v[2], v[3]);
    }
}

// ---------------- kernel 2: causal flash attention (tf32 mma.sync) ----------
// Block = 128 queries of one (b,h). 8 warps, each owns a 16-row strip.
// smem: Ks[64][68] (tf32, [key][d]), Vt[64][68] (tf32, [d][key]),
//       Ps[8 warps][16][68] (tf32 P)
#define KV_STRIDE 68
#define ATTN_SMEM_FLOATS (2 * 64 * KV_STRIDE + 8 * 16 * KV_STRIDE)
#define ATTN_SMEM_BYTES (ATTN_SMEM_FLOATS * 4)

__global__ __launch_bounds__(256) void attn_k() {
    extern __shared__ float sm[];
    unsigned* Ks = (unsigned*)sm;                       // 64*68
    unsigned* Vt = Ks + 64 * KV_STRIDE;                 // 64*68
    unsigned* Ps = Vt + 64 * KV_STRIDE;                 // 8*16*68

    const int tid = threadIdx.x;
    const int w = tid >> 5, lane = tid & 31;
    const int qr = lane >> 2, qc = lane & 3;            // quad-row, quad-col
    const int qi = (int)gridDim.x - 1 - (int)blockIdx.x; // heavy tiles first
    const int bh = blockIdx.y;
    const int b = bh / HH, h = bh % HH;
    const int q0 = qi * 128;

    const float* Qg = g_QKV + ((0 * BB + b) * HH + h) * TT * DD;
    const float* Kg = g_QKV + ((1 * BB + b) * HH + h) * TT * DD;
    const float* Vg = g_QKV + ((2 * BB + b) * HH + h) * TT * DD;

    // Q fragments: rows (q0 + 16w + qr, +8), fold 1/8 scale, tf32
    unsigned Qf[8][4];
    {
        const float* qb = &Qg[(q0 + w * 16 + qr) * DD];
#pragma unroll
        for (int kt = 0; kt < 8; kt++) {
            Qf[kt][0] = f2tf(qb[kt * 8 + qc] * 0.125f);
            Qf[kt][1] = f2tf(qb[8 * DD + kt * 8 + qc] * 0.125f);
            Qf[kt][2] = f2tf(qb[kt * 8 + qc + 4] * 0.125f);
            Qf[kt][3] = f2tf(qb[8 * DD + kt * 8 + qc + 4] * 0.125f);
        }
    }

    float Of[8][4] = {};
    float m0 = NEG, m1 = NEG, l0 = 0.0f, l1 = 0.0f;
    unsigned* Pw = Ps + w * 16 * KV_STRIDE;

    const int njt = 2 * qi + 2;
    for (int j = 0; j < njt; j++) {
        __syncthreads();   // all warps done with Ks/Vt before refill
        // fill K (natural [key][d]) and V (transposed [d][key]) as tf32
        {
            int key = tid >> 2, d0 = (tid & 3) << 4;
            const float* ks = &Kg[(j * 64 + key) * DD + d0];
            const float* vs = &Vg[(j * 64 + key) * DD + d0];
#pragma unroll
            for (int qq = 0; qq < 4; qq++) {
                float4 k4 = *(const float4*)&ks[qq * 4];
                float4 v4 = *(const float4*)&vs[qq * 4];
                unsigned* kd = &Ks[key * KV_STRIDE + d0 + qq * 4];
                kd[0] = f2tf(k4.x); kd[1] = f2tf(k4.y);
                kd[2] = f2tf(k4.z); kd[3] = f2tf(k4.w);
                int dd = d0 + qq * 4;
                Vt[(dd + 0) * KV_STRIDE + key] = f2tf(v4.x);
                Vt[(dd + 1) * KV_STRIDE + key] = f2tf(v4.y);
                Vt[(dd + 2) * KV_STRIDE + key] = f2tf(v4.z);
                Vt[(dd + 3) * KV_STRIDE + key] = f2tf(v4.w);
            }
        }
        __syncthreads();

        // S = Q K^T : 8 n-tiles (keys) x 8 k-steps (d)
        float Sf[8][4] = {};
#pragma unroll
        for (int nt = 0; nt < 8; nt++) {
#pragma unroll
            for (int kt = 0; kt < 8; kt++) {
                unsigned b0 = Ks[(nt * 8 + qr) * KV_STRIDE + kt * 8 + qc];
                unsigned b1 = Ks[(nt * 8 + qr) * KV_STRIDE + kt * 8 + qc + 4];
                mma_tf32(Sf[nt][0], Sf[nt][1], Sf[nt][2], Sf[nt][3],
                         Qf[kt][0], Qf[kt][1], Qf[kt][2], Qf[kt][3], b0, b1);
            }
        }

        // causal mask (last two k-tiles only)
        if (j >= njt - 2) {
            int r0g = q0 + w * 16 + qr, r1g = r0g + 8;
#pragma unroll
            for (int nt = 0; nt < 8; nt++) {
                int c0g = j * 64 + nt * 8 + 2 * qc;
                if (c0g > r0g)     Sf[nt][0] = NEG;
                if (c0g + 1 > r0g) Sf[nt][1] = NEG;
                if (c0g > r1g)     Sf[nt][2] = NEG;
                if (c0g + 1 > r1g) Sf[nt][3] = NEG;
            }
        }

        // online softmax; quad (4 lanes) owns each row
        float mx0 = NEG, mx1 = NEG;
#pragma unroll
        for (int nt = 0; nt < 8; nt++) {
            mx0 = fmaxf(mx0, fmaxf(Sf[nt][0], Sf[nt][1]));
            mx1 = fmaxf(mx1, fmaxf(Sf[nt][2], Sf[nt][3]));
        }
        mx0 = fmaxf(mx0, __shfl_xor_sync(0xffffffffu, mx0, 1));
        mx0 = fmaxf(mx0, __shfl_xor_sync(0xffffffffu, mx0, 2));
        mx1 = fmaxf(mx1, __shfl_xor_sync(0xffffffffu, mx1, 1));
        mx1 = fmaxf(mx1, __shfl_xor_sync(0xffffffffu, mx1, 2));
        float mn0 = fmaxf(m0, mx0), mn1 = fmaxf(m1, mx1);
        float al0 = __expf(m0 - mn0), al1 = __expf(m1 - mn1);
        m0 = mn0; m1 = mn1;
        float s0 = 0.0f, s1 = 0.0f;
#pragma unroll
        for (int nt = 0; nt < 8; nt++) {
            Sf[nt][0] = __expf(Sf[nt][0] - mn0); s0 += Sf[nt][0];
            Sf[nt][1] = __expf(Sf[nt][1] - mn0); s0 += Sf[nt][1];
            Sf[nt][2] = __expf(Sf[nt][2] - mn1); s1 += Sf[nt][2];
            Sf[nt][3] = __expf(Sf[nt][3] - mn1); s1 += Sf[nt][3];
        }
        s0 += __shfl_xor_sync(0xffffffffu, s0, 1);
        s0 += __shfl_xor_sync(0xffffffffu, s0, 2);
        s1 += __shfl_xor_sync(0xffffffffu, s1, 1);
        s1 += __shfl_xor_sync(0xffffffffu, s1, 2);
        l0 = l0 * al0 + s0;
        l1 = l1 * al1 + s1;
#pragma unroll
        for (int nt = 0; nt < 8; nt++) {
            Of[nt][0] *= al0; Of[nt][1] *= al0;
            Of[nt][2] *= al1; Of[nt][3] *= al1;
        }

        // store P (tf32) to per-warp smem
#pragma unroll
        for (int nt = 0; nt < 8; nt++) {
            unsigned* p0 = &Pw[qr * KV_STRIDE + nt * 8 + 2 * qc];
            p0[0] = f2tf(Sf[nt][0]); p0[1] = f2tf(Sf[nt][1]);
            unsigned* p1 = &Pw[(qr + 8) * KV_STRIDE + nt * 8 + 2 * qc];
            p1[0] = f2tf(Sf[nt][2]); p1[1] = f2tf(Sf[nt][3]);
        }
        __syncwarp();

        // O += P V : 8 k-steps (keys) x 8 n-tiles (d)
#pragma unroll
        for (int kt = 0; kt < 8; kt++) {
            unsigned a0 = Pw[qr * KV_STRIDE + kt * 8 + qc];
            unsigned a1 = Pw[(qr + 8) * KV_STRIDE + kt * 8 + qc];
            unsigned a2 = Pw[qr * KV_STRIDE + kt * 8 + qc + 4];
            unsigned a3 = Pw[(qr + 8) * KV_STRIDE + kt * 8 + qc + 4];
#pragma unroll
            for (int nt = 0; nt < 8; nt++) {
                unsigned b0 = Vt[(nt * 8 + qr) * KV_STRIDE + kt * 8 + qc];
                unsigned b1 = Vt[(nt * 8 + qr) * KV_STRIDE + kt * 8 + qc + 4];
                mma_tf32(Of[nt][0], Of[nt][1], Of[nt][2], Of[nt][3],
                         a0, a1, a2, a3, b0, b1);
            }
        }
    }

    // normalize + store to g_O [b*T+t][h*64+d]
    float il0 = 1.0f / l0, il1 = 1.0f / l1;
    int r0g = q0 + w * 16 + qr;
#pragma unroll
    for (int nt = 0; nt < 8; nt++) {
        int col = h * 64 + nt * 8 + 2 * qc;
        *(float2*)&g_O[(b * TT + r0g) * CC + col] =
            make_float2(Of[nt][0] * il0, Of[nt][1] * il0);
        *(float2*)&g_O[(b * TT + r0g + 8) * CC + col] =
            make_float2(Of[nt][2] * il1, Of[nt][3] * il1);
    }
}

// ---------------- kernel 3: output projection (fp32 SIMT) -------------------
__global__ __launch_bounds__(256) void out_proj_k(
        const float* __restrict__ wo,
        const float* __restrict__ bo,
        float* __restrict__ out) {
    __shared__ float As[16 * 128];
    __shared__ float Bs[16 * 64];
    const int tid = threadIdx.x;
    const int m0 = blockIdx.y * 128;
    const int n0 = blockIdx.x * 64;
    const int ty = tid >> 4, tx = tid & 15;
    const int row0 = ty << 3, col0 = tx << 2;
    const int lr = tid >> 1, lkb = (tid & 1) << 3;
    const int lbk = tid >> 4, lbn = (tid & 15) << 2;
    float acc[8][4] = {};

    for (int k0 = 0; k0 < CC; k0 += 16) {
        float4 a0 = *(const float4*)&g_O[(m0 + lr) * CC + k0 + lkb];
        float4 a1 = *(const float4*)&g_O[(m0 + lr) * CC + k0 + lkb + 4];
        float4 b0 = *(const float4*)&wo[(k0 + lbk) * CC + n0 + lbn];
        __syncthreads();
        {
            int xr = lr ^ ((lkb >> 3) << 4);
            As[(lkb + 0) * 128 + xr] = a0.x;
            As[(lkb + 1) * 128 + xr] = a0.y;
            As[(lkb + 2) * 128 + xr] = a0.z;
            As[(lkb + 3) * 128 + xr] = a0.w;
            As[(lkb + 4) * 128 + xr] = a1.x;
            As[(lkb + 5) * 128 + xr] = a1.y;
            As[(lkb + 6) * 128 + xr] = a1.z;
            As[(lkb + 7) * 128 + xr] = a1.w;
        }
        *(float4*)&Bs[lbk * 64 + lbn] = b0;
        __syncthreads();
#pragma unroll
        for (int k = 0; k < 16; k++) {
            int rb = row0 ^ ((k >> 3) << 4);
            float4 av0 = *(float4*)&As[k * 128 + rb];
            float4 av1 = *(float4*)&As[k * 128 + rb + 4];
            float4 bv4 = *(float4*)&Bs[k * 64 + col0];
            float a[8] = {av0.x, av0.y, av0.z, av0.w, av1.x, av1.y, av1.z, av1.w};
            float b[4] = {bv4.x, bv4.y, bv4.z, bv4.w};
#pragma unroll
            for (int i = 0; i < 8; i++)
#pragma unroll
                for (int j = 0; j < 4; j++)
                    acc[i][j] = fmaf(a[i], b[j], acc[i][j]);
        }
    }

    float bias4[4];
#pragma unroll
    for (int j = 0; j < 4; j++) bias4[j] = bo[n0 + col0 + j];
#pragma unroll
    for (int i = 0; i < 8; i++) {
        int m = m0 + row0 + i;
        float* dst = &out[m * CC + n0 + col0];
        *(float4*)dst = make_float4(acc[i][0] + bias4[0], acc[i][1] + bias4[1],
                                    acc[i][2] + bias4[2], acc[i][3] + bias4[3]);
    }
}

// ---------------- launcher ---------------------------------------------------
extern "C" void kernel_launch(void* const* d_in, const int* in_sizes, int n_in,
                              void* d_out, int out_size) {
    const float* x  = (const float*)d_in[0];
    const float* wq = (const float*)d_in[1];
    const float* bq = (const float*)d_in[2];
    const float* wk = (const float*)d_in[3];
    const float* bk = (const float*)d_in[4];
    const float* wv = (const float*)d_in[5];
    const float* bv = (const float*)d_in[6];
    const float* wo = (const float*)d_in[7];
    const float* bo = (const float*)d_in[8];
    float* out = (float*)d_out;

    cudaFuncSetAttribute(attn_k, cudaFuncAttributeMaxDynamicSharedMemorySize,
                         ATTN_SMEM_BYTES);

    pack_w_k<<<(CC * NQKV + 255) / 256, 256>>>(wq, wk, wv);
    rope_table_k<<<(TT * 32 + 255) / 256, 256>>>();
    qkv_rope_k<<<dim3(NQKV / 64, (BB * TT) / 128), 256>>>(x, bq, bk, bv);
    attn_k<<<dim3(TT / 128, BB * HH), 256, ATTN_SMEM_BYTES>>>();
    out_proj_k<<<dim3(CC / 64, (BB * TT) / 128), 256>>>(wo, bo, out);
}

// round 6
// speedup vs baseline: 2.1590x; 1.2445x over previous
#include <cuda_runtime.h>
#include <math.h>

#define BB 2
#define TT 2048
#define HH 12
#define DD 64
#define CC 768
#define NQKV 2304
#define NEG (-1e30f)

// ---------------- scratch (device globals; no allocations allowed) ----------
__device__ float g_Wqkv[CC * NQKV];                 // packed [K=768][N=2304]
__device__ float g_QKV[3 * BB * HH * TT * DD];      // [which][b][h][t][d]
__device__ float g_O[BB * TT * CC];                 // [b*T + t][h*64 + d]
__device__ float g_cos[TT * 32];
__device__ float g_sin[TT * 32];

// ---------------- helpers ----------------------------------------------------
__device__ __forceinline__ unsigned f2tf(float f) {
    unsigned u;
    asm("cvt.rna.tf32.f32 %0, %1;" : "=r"(u) : "f"(f));
    return u;
}

__device__ __forceinline__ void mma_tf32(
        float& c0, float& c1, float& c2, float& c3,
        unsigned a0, unsigned a1, unsigned a2, unsigned a3,
        unsigned b0, unsigned b1) {
    asm("mma.sync.aligned.m16n8k8.row.col.f32.tf32.tf32.f32 "
        "{%0,%1,%2,%3}, {%4,%5,%6,%7}, {%8,%9}, {%0,%1,%2,%3};"
        : "+f"(c0), "+f"(c1), "+f"(c2), "+f"(c3)
        : "r"(a0), "r"(a1), "r"(a2), "r"(a3), "r"(b0), "r"(b1));
}

// ---------------- kernel 0a: pack QKV weights into one B matrix -------------
__global__ void pack_w_k(const float* __restrict__ wq,
                         const float* __restrict__ wk,
                         const float* __restrict__ wv) {
    int idx = blockIdx.x * 256 + threadIdx.x;
    if (idx >= CC * NQKV) return;
    int c = idx / NQKV, n = idx - c * NQKV;
    int which = n / 768, hd = n - which * 768;
    int h = hd >> 6, d = hd & 63;
    const float* w = (which == 0) ? wq : (which == 1) ? wk : wv;
    g_Wqkv[idx] = w[(h * CC + c) * DD + d];
}

// ---------------- kernel 0b: rope cos/sin table -----------------------------
__global__ void rope_table_k() {
    int idx = blockIdx.x * 256 + threadIdx.x;
    if (idx >= TT * 32) return;
    int t = idx >> 5, i = idx & 31;
    double e = (double)i * 0.41524101186092028;   // log2(10000)/32
    float inv = exp2f((float)(-e));
    float ang = (float)t * inv;
    float s, c;
    sincosf(ang, &s, &c);
    g_cos[idx] = c;
    g_sin[idx] = s;
}

// ---------------- tf32 GEMM tiles: 128x64, 8 warps, warp = 16 rows ----------
#define XS_STRIDE 20
#define WS_STRIDE 68

// ---------------- kernel 1: QKV GEMM + bias + RoPE (tf32 mma) ---------------
__global__ __launch_bounds__(256) void qkv_tc_k(
        const float* __restrict__ x,
        const float* __restrict__ bq,
        const float* __restrict__ bk,
        const float* __restrict__ bv) {
    __shared__ unsigned Xs[128 * XS_STRIDE];   // [row][k], tf32
    __shared__ unsigned Ws[16 * WS_STRIDE];    // [k][n], tf32
    const int tid = threadIdx.x;
    const int w = tid >> 5, lane = tid & 31;
    const int qr = lane >> 2, qc = lane & 3;
    const int m0 = blockIdx.y * 128;
    const int n0 = blockIdx.x * 64;
    const int lrow = tid >> 1, lkb = (tid & 1) << 3;   // X: row, k-base
    const int lkr = tid >> 4, lnb = (tid & 15) << 2;   // W: k-row, n-base

    float Cf[8][4] = {};

    for (int k0 = 0; k0 < CC; k0 += 16) {
        float4 a0 = *(const float4*)&x[(m0 + lrow) * CC + k0 + lkb];
        float4 a1 = *(const float4*)&x[(m0 + lrow) * CC + k0 + lkb + 4];
        float4 b4 = *(const float4*)&g_Wqkv[(k0 + lkr) * NQKV + n0 + lnb];
        __syncthreads();
        {
            unsigned* xd = &Xs[lrow * XS_STRIDE + lkb];
            xd[0] = f2tf(a0.x); xd[1] = f2tf(a0.y);
            xd[2] = f2tf(a0.z); xd[3] = f2tf(a0.w);
            xd[4] = f2tf(a1.x); xd[5] = f2tf(a1.y);
            xd[6] = f2tf(a1.z); xd[7] = f2tf(a1.w);
            unsigned* wd = &Ws[lkr * WS_STRIDE + lnb];
            wd[0] = f2tf(b4.x); wd[1] = f2tf(b4.y);
            wd[2] = f2tf(b4.z); wd[3] = f2tf(b4.w);
        }
        __syncthreads();
#pragma unroll
        for (int kt = 0; kt < 2; kt++) {
            int abase = (w * 16 + qr) * XS_STRIDE + kt * 8 + qc;
            unsigned fa0 = Xs[abase];
            unsigned fa1 = Xs[abase + 8 * XS_STRIDE];
            unsigned fa2 = Xs[abase + 4];
            unsigned fa3 = Xs[abase + 8 * XS_STRIDE + 4];
            int bb0 = (kt * 8 + qc) * WS_STRIDE + qr;
            int bb1 = (kt * 8 + qc + 4) * WS_STRIDE + qr;
#pragma unroll
            for (int nt = 0; nt < 8; nt++) {
                mma_tf32(Cf[nt][0], Cf[nt][1], Cf[nt][2], Cf[nt][3],
                         fa0, fa1, fa2, fa3, Ws[bb0 + nt * 8], Ws[bb1 + nt * 8]);
            }
        }
    }

    // epilogue: bias + rope + scatter to g_QKV
    const int which = n0 / 768;
    const int h = (n0 % 768) >> 6;
    const float* bias = (which == 0) ? bq : (which == 1) ? bk : bv;
    const int r0 = m0 + w * 16 + qr;
#pragma unroll
    for (int nt = 0; nt < 8; nt++) {
        int d = nt * 8 + 2 * qc;
        float bv0 = bias[h * 64 + d], bv1 = bias[h * 64 + d + 1];
        int ii = nt * 4 + qc;
#pragma unroll
        for (int half = 0; half < 2; half++) {
            int r = r0 + half * 8;
            int bb = r >> 11, t = r & 2047;
            float v0 = Cf[nt][2 * half + 0] + bv0;
            float v1 = Cf[nt][2 * half + 1] + bv1;
            if (which < 2) {
                float c = g_cos[t * 32 + ii];
                float s = g_sin[t * 32 + ii];
                float nv0 = v0 * c - v1 * s;
                float nv1 = v0 * s + v1 * c;
                v0 = nv0; v1 = nv1;
            }
            *(float2*)&g_QKV[(((which * BB + bb) * HH + h) * TT + t) * DD + d] =
                make_float2(v0, v1);
        }
    }
}

// ---------------- kernel 2: causal flash attention (tf32 mma.sync) ----------
#define KV_STRIDE 68
#define ATTN_SMEM_FLOATS (2 * 64 * KV_STRIDE + 8 * 16 * KV_STRIDE)
#define ATTN_SMEM_BYTES (ATTN_SMEM_FLOATS * 4)

__global__ __launch_bounds__(256) void attn_k() {
    extern __shared__ float sm[];
    unsigned* Ks = (unsigned*)sm;                       // 64*68
    unsigned* Vt = Ks + 64 * KV_STRIDE;                 // 64*68
    unsigned* Ps = Vt + 64 * KV_STRIDE;                 // 8*16*68

    const int tid = threadIdx.x;
    const int w = tid >> 5, lane = tid & 31;
    const int qr = lane >> 2, qc = lane & 3;
    const int qi = (int)gridDim.x - 1 - (int)blockIdx.x; // heavy tiles first
    const int bh = blockIdx.y;
    const int b = bh / HH, h = bh % HH;
    const int q0 = qi * 128;

    const float* Qg = g_QKV + ((0 * BB + b) * HH + h) * TT * DD;
    const float* Kg = g_QKV + ((1 * BB + b) * HH + h) * TT * DD;
    const float* Vg = g_QKV + ((2 * BB + b) * HH + h) * TT * DD;

    unsigned Qf[8][4];
    {
        const float* qb = &Qg[(q0 + w * 16 + qr) * DD];
#pragma unroll
        for (int kt = 0; kt < 8; kt++) {
            Qf[kt][0] = f2tf(qb[kt * 8 + qc] * 0.125f);
            Qf[kt][1] = f2tf(qb[8 * DD + kt * 8 + qc] * 0.125f);
            Qf[kt][2] = f2tf(qb[kt * 8 + qc + 4] * 0.125f);
            Qf[kt][3] = f2tf(qb[8 * DD + kt * 8 + qc + 4] * 0.125f);
        }
    }

    float Of[8][4] = {};
    float m0 = NEG, m1 = NEG, l0 = 0.0f, l1 = 0.0f;
    unsigned* Pw = Ps + w * 16 * KV_STRIDE;

    const int njt = 2 * qi + 2;
    for (int j = 0; j < njt; j++) {
        __syncthreads();
        {
            int key = tid >> 2, d0 = (tid & 3) << 4;
            const float* ks = &Kg[(j * 64 + key) * DD + d0];
            const float* vs = &Vg[(j * 64 + key) * DD + d0];
#pragma unroll
            for (int qq = 0; qq < 4; qq++) {
                float4 k4 = *(const float4*)&ks[qq * 4];
                float4 v4 = *(const float4*)&vs[qq * 4];
                unsigned* kd = &Ks[key * KV_STRIDE + d0 + qq * 4];
                kd[0] = f2tf(k4.x); kd[1] = f2tf(k4.y);
                kd[2] = f2tf(k4.z); kd[3] = f2tf(k4.w);
                int dd = d0 + qq * 4;
                Vt[(dd + 0) * KV_STRIDE + key] = f2tf(v4.x);
                Vt[(dd + 1) * KV_STRIDE + key] = f2tf(v4.y);
                Vt[(dd + 2) * KV_STRIDE + key] = f2tf(v4.z);
                Vt[(dd + 3) * KV_STRIDE + key] = f2tf(v4.w);
            }
        }
        __syncthreads();

        float Sf[8][4] = {};
#pragma unroll
        for (int nt = 0; nt < 8; nt++) {
#pragma unroll
            for (int kt = 0; kt < 8; kt++) {
                unsigned b0 = Ks[(nt * 8 + qr) * KV_STRIDE + kt * 8 + qc];
                unsigned b1 = Ks[(nt * 8 + qr) * KV_STRIDE + kt * 8 + qc + 4];
                mma_tf32(Sf[nt][0], Sf[nt][1], Sf[nt][2], Sf[nt][3],
                         Qf[kt][0], Qf[kt][1], Qf[kt][2], Qf[kt][3], b0, b1);
            }
        }

        if (j >= njt - 2) {
            int r0g = q0 + w * 16 + qr, r1g = r0g + 8;
#pragma unroll
            for (int nt = 0; nt < 8; nt++) {
                int c0g = j * 64 + nt * 8 + 2 * qc;
                if (c0g > r0g)     Sf[nt][0] = NEG;
                if (c0g + 1 > r0g) Sf[nt][1] = NEG;
                if (c0g > r1g)     Sf[nt][2] = NEG;
                if (c0g + 1 > r1g) Sf[nt][3] = NEG;
            }
        }

        float mx0 = NEG, mx1 = NEG;
#pragma unroll
        for (int nt = 0; nt < 8; nt++) {
            mx0 = fmaxf(mx0, fmaxf(Sf[nt][0], Sf[nt][1]));
            mx1 = fmaxf(mx1, fmaxf(Sf[nt][2], Sf[nt][3]));
        }
        mx0 = fmaxf(mx0, __shfl_xor_sync(0xffffffffu, mx0, 1));
        mx0 = fmaxf(mx0, __shfl_xor_sync(0xffffffffu, mx0, 2));
        mx1 = fmaxf(mx1, __shfl_xor_sync(0xffffffffu, mx1, 1));
        mx1 = fmaxf(mx1, __shfl_xor_sync(0xffffffffu, mx1, 2));
        float mn0 = fmaxf(m0, mx0), mn1 = fmaxf(m1, mx1);
        float al0 = __expf(m0 - mn0), al1 = __expf(m1 - mn1);
        m0 = mn0; m1 = mn1;
        float s0 = 0.0f, s1 = 0.0f;
#pragma unroll
        for (int nt = 0; nt < 8; nt++) {
            Sf[nt][0] = __expf(Sf[nt][0] - mn0); s0 += Sf[nt][0];
            Sf[nt][1] = __expf(Sf[nt][1] - mn0); s0 += Sf[nt][1];
            Sf[nt][2] = __expf(Sf[nt][2] - mn1); s1 += Sf[nt][2];
            Sf[nt][3] = __expf(Sf[nt][3] - mn1); s1 += Sf[nt][3];
        }
        s0 += __shfl_xor_sync(0xffffffffu, s0, 1);
        s0 += __shfl_xor_sync(0xffffffffu, s0, 2);
        s1 += __shfl_xor_sync(0xffffffffu, s1, 1);
        s1 += __shfl_xor_sync(0xffffffffu, s1, 2);
        l0 = l0 * al0 + s0;
        l1 = l1 * al1 + s1;
#pragma unroll
        for (int nt = 0; nt < 8; nt++) {
            Of[nt][0] *= al0; Of[nt][1] *= al0;
            Of[nt][2] *= al1; Of[nt][3] *= al1;
        }

#pragma unroll
        for (int nt = 0; nt < 8; nt++) {
            unsigned* p0 = &Pw[qr * KV_STRIDE + nt * 8 + 2 * qc];
            p0[0] = f2tf(Sf[nt][0]); p0[1] = f2tf(Sf[nt][1]);
            unsigned* p1 = &Pw[(qr + 8) * KV_STRIDE + nt * 8 + 2 * qc];
            p1[0] = f2tf(Sf[nt][2]); p1[1] = f2tf(Sf[nt][3]);
        }
        __syncwarp();

#pragma unroll
        for (int kt = 0; kt < 8; kt++) {
            unsigned a0 = Pw[qr * KV_STRIDE + kt * 8 + qc];
            unsigned a1 = Pw[(qr + 8) * KV_STRIDE + kt * 8 + qc];
            unsigned a2 = Pw[qr * KV_STRIDE + kt * 8 + qc + 4];
            unsigned a3 = Pw[(qr + 8) * KV_STRIDE + kt * 8 + qc + 4];
#pragma unroll
            for (int nt = 0; nt < 8; nt++) {
                unsigned b0 = Vt[(nt * 8 + qr) * KV_STRIDE + kt * 8 + qc];
                unsigned b1 = Vt[(nt * 8 + qr) * KV_STRIDE + kt * 8 + qc + 4];
                mma_tf32(Of[nt][0], Of[nt][1], Of[nt][2], Of[nt][3],
                         a0, a1, a2, a3, b0, b1);
            }
        }
    }

    float il0 = 1.0f / l0, il1 = 1.0f / l1;
    int r0g = q0 + w * 16 + qr;
#pragma unroll
    for (int nt = 0; nt < 8; nt++) {
        int col = h * 64 + nt * 8 + 2 * qc;
        *(float2*)&g_O[(b * TT + r0g) * CC + col] =
            make_float2(Of[nt][0] * il0, Of[nt][1] * il0);
        *(float2*)&g_O[(b * TT + r0g + 8) * CC + col] =
            make_float2(Of[nt][2] * il1, Of[nt][3] * il1);
    }
}

// ---------------- kernel 3: output projection (tf32 mma) --------------------
__global__ __launch_bounds__(256) void out_proj_tc_k(
        const float* __restrict__ wo,
        const float* __restrict__ bo,
        float* __restrict__ out) {
    __shared__ unsigned Xs[128 * XS_STRIDE];   // [row][k]
    __shared__ unsigned Ws[16 * WS_STRIDE];    // [k][n]
    const int tid = threadIdx.x;
    const int w = tid >> 5, lane = tid & 31;
    const int qr = lane >> 2, qc = lane & 3;
    const int m0 = blockIdx.y * 128;
    const int n0 = blockIdx.x * 64;
    const int lrow = tid >> 1, lkb = (tid & 1) << 3;
    const int lkr = tid >> 4, lnb = (tid & 15) << 2;

    float Cf[8][4] = {};

    for (int k0 = 0; k0 < CC; k0 += 16) {
        float4 a0 = *(const float4*)&g_O[(m0 + lrow) * CC + k0 + lkb];
        float4 a1 = *(const float4*)&g_O[(m0 + lrow) * CC + k0 + lkb + 4];
        float4 b4 = *(const float4*)&wo[(k0 + lkr) * CC + n0 + lnb];
        __syncthreads();
        {
            unsigned* xd = &Xs[lrow * XS_STRIDE + lkb];
            xd[0] = f2tf(a0.x); xd[1] = f2tf(a0.y);
            xd[2] = f2tf(a0.z); xd[3] = f2tf(a0.w);
            xd[4] = f2tf(a1.x); xd[5] = f2tf(a1.y);
            xd[6] = f2tf(a1.z); xd[7] = f2tf(a1.w);
            unsigned* wd = &Ws[lkr * WS_STRIDE + lnb];
            wd[0] = f2tf(b4.x); wd[1] = f2tf(b4.y);
            wd[2] = f2tf(b4.z); wd[3] = f2tf(b4.w);
        }
        __syncthreads();
#pragma unroll
        for (int kt = 0; kt < 2; kt++) {
            int abase = (w * 16 + qr) * XS_STRIDE + kt * 8 + qc;
            unsigned fa0 = Xs[abase];
            unsigned fa1 = Xs[abase + 8 * XS_STRIDE];
            unsigned fa2 = Xs[abase + 4];
            unsigned fa3 = Xs[abase + 8 * XS_STRIDE + 4];
            int bb0 = (kt * 8 + qc) * WS_STRIDE + qr;
            int bb1 = (kt * 8 + qc + 4) * WS_STRIDE + qr;
#pragma unroll
            for (int nt = 0; nt < 8; nt++) {
                mma_tf32(Cf[nt][0], Cf[nt][1], Cf[nt][2], Cf[nt][3],
                         fa0, fa1, fa2, fa3, Ws[bb0 + nt * 8], Ws[bb1 + nt * 8]);
            }
        }
    }

    const int r0 = m0 + w * 16 + qr;
#pragma unroll
    for (int nt = 0; nt < 8; nt++) {
        int n = n0 + nt * 8 + 2 * qc;
        float bv0 = bo[n], bv1 = bo[n + 1];
        *(float2*)&out[r0 * CC + n] =
            make_float2(Cf[nt][0] + bv0, Cf[nt][1] + bv1);
        *(float2*)&out[(r0 + 8) * CC + n] =
            make_float2(Cf[nt][2] + bv0, Cf[nt][3] + bv1);
    }
}

// ---------------- launcher ---------------------------------------------------
extern "C" void kernel_launch(void* const* d_in, const int* in_sizes, int n_in,
                              void* d_out, int out_size) {
    const float* x  = (const float*)d_in[0];
    const float* wq = (const float*)d_in[1];
    const float* bq = (const float*)d_in[2];
    const float* wk = (const float*)d_in[3];
    const float* bk = (const float*)d_in[4];
    const float* wv = (const float*)d_in[5];
    const float* bv = (const float*)d_in[6];
    const float* wo = (const float*)d_in[7];
    const float* bo = (const float*)d_in[8];
    float* out = (float*)d_out;

    cudaFuncSetAttribute(attn_k, cudaFuncAttributeMaxDynamicSharedMemorySize,
                         ATTN_SMEM_BYTES);

    pack_w_k<<<(CC * NQKV + 255) / 256, 256>>>(wq, wk, wv);
    rope_table_k<<<(TT * 32 + 255) / 256, 256>>>();
    qkv_tc_k<<<dim3(NQKV / 64, (BB * TT) / 128), 256>>>(x, bq, bk, bv);
    attn_k<<<dim3(TT / 128, BB * HH), 256, ATTN_SMEM_BYTES>>>();
    out_proj_tc_k<<<dim3(CC / 64, (BB * TT) / 128), 256>>>(wo, bo, out);
}

// round 7
// speedup vs baseline: 2.2810x; 1.0565x over previous
#include <cuda_runtime.h>
#include <math.h>

#define BB 2
#define TT 2048
#define HH 12
#define DD 64
#define CC 768
#define NQKV 2304
#define NEG (-1e30f)

// ---------------- scratch (device globals; no allocations allowed) ----------
__device__ unsigned g_Wqkv[CC * NQKV];              // tf32 [K=768][N=2304]
__device__ unsigned g_Wo[CC * CC];                  // tf32 [K=768][N=768]
__device__ unsigned g_Xtf[BB * TT * CC];            // tf32 x
__device__ float    g_QKV[3 * BB * HH * TT * DD];   // [which][b][h][t][d]
__device__ unsigned g_Otf[BB * TT * CC];            // tf32 O [b*T+t][h*64+d]
__device__ float    g_cos[TT * 32];
__device__ float    g_sin[TT * 32];

// ---------------- helpers ----------------------------------------------------
__device__ __forceinline__ unsigned f2tf(float f) {
    unsigned u;
    asm("cvt.rna.tf32.f32 %0, %1;" : "=r"(u) : "f"(f));
    return u;
}

__device__ __forceinline__ void mma_tf32(
        float& c0, float& c1, float& c2, float& c3,
        unsigned a0, unsigned a1, unsigned a2, unsigned a3,
        unsigned b0, unsigned b1) {
    asm("mma.sync.aligned.m16n8k8.row.col.f32.tf32.tf32.f32 "
        "{%0,%1,%2,%3}, {%4,%5,%6,%7}, {%8,%9}, {%0,%1,%2,%3};"
        : "+f"(c0), "+f"(c1), "+f"(c2), "+f"(c3)
        : "r"(a0), "r"(a1), "r"(a2), "r"(a3), "r"(b0), "r"(b1));
}

// ---------------- kernel 0a: pack QKV weights (tf32) ------------------------
__global__ void pack_w_k(const float* __restrict__ wq,
                         const float* __restrict__ wk,
                         const float* __restrict__ wv) {
    int idx = blockIdx.x * 256 + threadIdx.x;
    if (idx >= CC * NQKV) return;
    int c = idx / NQKV, n = idx - c * NQKV;
    int which = n / 768, hd = n - which * 768;
    int h = hd >> 6, d = hd & 63;
    const float* w = (which == 0) ? wq : (which == 1) ? wk : wv;
    g_Wqkv[idx] = f2tf(w[(h * CC + c) * DD + d]);
}

// ---------------- kernel 0b: W_O pack (layout already [k][n]) ---------------
__global__ void pack_wo_k(const float* __restrict__ wo) {
    int idx = blockIdx.x * 256 + threadIdx.x;
    if (idx >= CC * CC) return;
    g_Wo[idx] = f2tf(wo[idx]);
}

// ---------------- kernel 0c: x -> tf32 ---------------------------------------
__global__ void xconv_k(const float* __restrict__ x) {
    int idx = blockIdx.x * 256 + threadIdx.x;
    if (idx >= BB * TT * CC) return;
    g_Xtf[idx] = f2tf(x[idx]);
}

// ---------------- kernel 0d: rope cos/sin table -----------------------------
__global__ void rope_table_k() {
    int idx = blockIdx.x * 256 + threadIdx.x;
    if (idx >= TT * 32) return;
    int t = idx >> 5, i = idx & 31;
    double e = (double)i * 0.41524101186092028;   // log2(10000)/32
    float inv = exp2f((float)(-e));
    float ang = (float)t * inv;
    float s, c;
    sincosf(ang, &s, &c);
    g_cos[idx] = c;
    g_sin[idx] = s;
}

// ---------------- tf32 GEMM: 128x64 tile, chunk 32, double-buffered ---------
#define XSTR 36
#define WSTR 72
#define GEMM_SMEM_UINTS (2 * 128 * XSTR + 2 * 32 * WSTR)
#define GEMM_SMEM_BYTES (GEMM_SMEM_UINTS * 4)

// ---------------- kernel 1: QKV GEMM + bias + RoPE (tf32 mma) ---------------
__global__ __launch_bounds__(256) void qkv_tc_k(
        const float* __restrict__ bq,
        const float* __restrict__ bk,
        const float* __restrict__ bv) {
    extern __shared__ unsigned smg[];
    unsigned* Xs = smg;                        // 2 * 128*36
    unsigned* Ws = smg + 2 * 128 * XSTR;       // 2 * 32*72
    const int tid = threadIdx.x;
    const int w = tid >> 5, lane = tid & 31;
    const int qr = lane >> 2, qc = lane & 3;
    const int m0 = blockIdx.y * 128;
    const int n0 = blockIdx.x * 64;
    const int lrow = tid >> 1, lkb = (tid & 1) << 4;   // X: row, 16 k
    const int lkr = tid >> 3, lnb = (tid & 7) << 3;    // W: k-row, 8 n

    uint4 xr[4], wr[2];
#pragma unroll
    for (int q = 0; q < 4; q++)
        xr[q] = *(const uint4*)&g_Xtf[(m0 + lrow) * CC + lkb + q * 4];
#pragma unroll
    for (int q = 0; q < 2; q++)
        wr[q] = *(const uint4*)&g_Wqkv[lkr * NQKV + n0 + lnb + q * 4];
    {
        unsigned* xd = &Xs[lrow * XSTR + lkb];
#pragma unroll
        for (int q = 0; q < 4; q++) *(uint4*)&xd[q * 4] = xr[q];
        unsigned* wd = &Ws[lkr * WSTR + lnb];
#pragma unroll
        for (int q = 0; q < 2; q++) *(uint4*)&wd[q * 4] = wr[q];
    }
    __syncthreads();

    float Cf[8][4] = {};
    const int NCH = CC / 32;   // 24
    for (int c = 0; c < NCH; c++) {
        if (c + 1 < NCH) {
            int k0 = (c + 1) * 32;
#pragma unroll
            for (int q = 0; q < 4; q++)
                xr[q] = *(const uint4*)&g_Xtf[(m0 + lrow) * CC + k0 + lkb + q * 4];
#pragma unroll
            for (int q = 0; q < 2; q++)
                wr[q] = *(const uint4*)&g_Wqkv[(k0 + lkr) * NQKV + n0 + lnb + q * 4];
        }
        const unsigned* Xb = Xs + (c & 1) * 128 * XSTR;
        const unsigned* Wb = Ws + (c & 1) * 32 * WSTR;
#pragma unroll
        for (int kt = 0; kt < 4; kt++) {
            int abase = (w * 16 + qr) * XSTR + kt * 8 + qc;
            unsigned fa0 = Xb[abase];
            unsigned fa1 = Xb[abase + 8 * XSTR];
            unsigned fa2 = Xb[abase + 4];
            unsigned fa3 = Xb[abase + 8 * XSTR + 4];
            int bb0 = (kt * 8 + qc) * WSTR + qr;
            int bb1 = bb0 + 4 * WSTR;
#pragma unroll
            for (int nt = 0; nt < 8; nt++)
                mma_tf32(Cf[nt][0], Cf[nt][1], Cf[nt][2], Cf[nt][3],
                         fa0, fa1, fa2, fa3, Wb[bb0 + nt * 8], Wb[bb1 + nt * 8]);
        }
        if (c + 1 < NCH) {
            unsigned* Xn = Xs + ((c + 1) & 1) * 128 * XSTR;
            unsigned* Wn = Ws + ((c + 1) & 1) * 32 * WSTR;
            unsigned* xd = &Xn[lrow * XSTR + lkb];
#pragma unroll
            for (int q = 0; q < 4; q++) *(uint4*)&xd[q * 4] = xr[q];
            unsigned* wd = &Wn[lkr * WSTR + lnb];
#pragma unroll
            for (int q = 0; q < 2; q++) *(uint4*)&wd[q * 4] = wr[q];
            __syncthreads();
        }
    }

    // epilogue: bias + rope + scatter to g_QKV
    const int which = n0 / 768;
    const int h = (n0 % 768) >> 6;
    const float* bias = (which == 0) ? bq : (which == 1) ? bk : bv;
    const int r0 = m0 + w * 16 + qr;
#pragma unroll
    for (int nt = 0; nt < 8; nt++) {
        int d = nt * 8 + 2 * qc;
        float bv0 = bias[h * 64 + d], bv1 = bias[h * 64 + d + 1];
        int ii = nt * 4 + qc;
#pragma unroll
        for (int half = 0; half < 2; half++) {
            int r = r0 + half * 8;
            int bb = r >> 11, t = r & 2047;
            float v0 = Cf[nt][2 * half + 0] + bv0;
            float v1 = Cf[nt][2 * half + 1] + bv1;
            if (which < 2) {
                float cth = g_cos[t * 32 + ii];
                float sth = g_sin[t * 32 + ii];
                float nv0 = v0 * cth - v1 * sth;
                float nv1 = v0 * sth + v1 * cth;
                v0 = nv0; v1 = nv1;
            }
            *(float2*)&g_QKV[(((which * BB + bb) * HH + h) * TT + t) * DD + d] =
                make_float2(v0, v1);
        }
    }
}

// ---------------- kernel 2: causal flash attention (tf32 mma.sync) ----------
#define KV_STRIDE 68
#define ATTN_SMEM_FLOATS (2 * 64 * KV_STRIDE + 8 * 16 * KV_STRIDE)
#define ATTN_SMEM_BYTES (ATTN_SMEM_FLOATS * 4)

__global__ __launch_bounds__(256) void attn_k() {
    extern __shared__ float sm[];
    unsigned* Ks = (unsigned*)sm;                       // 64*68
    unsigned* Vt = Ks + 64 * KV_STRIDE;                 // 64*68
    unsigned* Ps = Vt + 64 * KV_STRIDE;                 // 8*16*68

    const int tid = threadIdx.x;
    const int w = tid >> 5, lane = tid & 31;
    const int qr = lane >> 2, qc = lane & 3;
    const int qi = (int)gridDim.x - 1 - (int)blockIdx.x; // heavy tiles first
    const int bh = blockIdx.y;
    const int b = bh / HH, h = bh % HH;
    const int q0 = qi * 128;

    const float* Qg = g_QKV + ((0 * BB + b) * HH + h) * TT * DD;
    const float* Kg = g_QKV + ((1 * BB + b) * HH + h) * TT * DD;
    const float* Vg = g_QKV + ((2 * BB + b) * HH + h) * TT * DD;

    unsigned Qf[8][4];
    {
        const float* qb = &Qg[(q0 + w * 16 + qr) * DD];
#pragma unroll
        for (int kt = 0; kt < 8; kt++) {
            Qf[kt][0] = f2tf(qb[kt * 8 + qc] * 0.125f);
            Qf[kt][1] = f2tf(qb[8 * DD + kt * 8 + qc] * 0.125f);
            Qf[kt][2] = f2tf(qb[kt * 8 + qc + 4] * 0.125f);
            Qf[kt][3] = f2tf(qb[8 * DD + kt * 8 + qc + 4] * 0.125f);
        }
    }

    float Of[8][4] = {};
    float m0 = NEG, m1 = NEG, l0 = 0.0f, l1 = 0.0f;
    unsigned* Pw = Ps + w * 16 * KV_STRIDE;

    const int njt = 2 * qi + 2;
    for (int j = 0; j < njt; j++) {
        __syncthreads();
        {
            int key = tid >> 2, d0 = (tid & 3) << 4;
            const float* ks = &Kg[(j * 64 + key) * DD + d0];
            const float* vs = &Vg[(j * 64 + key) * DD + d0];
#pragma unroll
            for (int qq = 0; qq < 4; qq++) {
                float4 k4 = *(const float4*)&ks[qq * 4];
                float4 v4 = *(const float4*)&vs[qq * 4];
                unsigned* kd = &Ks[key * KV_STRIDE + d0 + qq * 4];
                kd[0] = f2tf(k4.x); kd[1] = f2tf(k4.y);
                kd[2] = f2tf(k4.z); kd[3] = f2tf(k4.w);
                int dd = d0 + qq * 4;
                Vt[(dd + 0) * KV_STRIDE + key] = f2tf(v4.x);
                Vt[(dd + 1) * KV_STRIDE + key] = f2tf(v4.y);
                Vt[(dd + 2) * KV_STRIDE + key] = f2tf(v4.z);
                Vt[(dd + 3) * KV_STRIDE + key] = f2tf(v4.w);
            }
        }
        __syncthreads();

        float Sf[8][4] = {};
#pragma unroll
        for (int nt = 0; nt < 8; nt++) {
#pragma unroll
            for (int kt = 0; kt < 8; kt++) {
                unsigned b0 = Ks[(nt * 8 + qr) * KV_STRIDE + kt * 8 + qc];
                unsigned b1 = Ks[(nt * 8 + qr) * KV_STRIDE + kt * 8 + qc + 4];
                mma_tf32(Sf[nt][0], Sf[nt][1], Sf[nt][2], Sf[nt][3],
                         Qf[kt][0], Qf[kt][1], Qf[kt][2], Qf[kt][3], b0, b1);
            }
        }

        if (j >= njt - 2) {
            int r0g = q0 + w * 16 + qr, r1g = r0g + 8;
#pragma unroll
            for (int nt = 0; nt < 8; nt++) {
                int c0g = j * 64 + nt * 8 + 2 * qc;
                if (c0g > r0g)     Sf[nt][0] = NEG;
                if (c0g + 1 > r0g) Sf[nt][1] = NEG;
                if (c0g > r1g)     Sf[nt][2] = NEG;
                if (c0g + 1 > r1g) Sf[nt][3] = NEG;
            }
        }

        float mx0 = NEG, mx1 = NEG;
#pragma unroll
        for (int nt = 0; nt < 8; nt++) {
            mx0 = fmaxf(mx0, fmaxf(Sf[nt][0], Sf[nt][1]));
            mx1 = fmaxf(mx1, fmaxf(Sf[nt][2], Sf[nt][3]));
        }
        mx0 = fmaxf(mx0, __shfl_xor_sync(0xffffffffu, mx0, 1));
        mx0 = fmaxf(mx0, __shfl_xor_sync(0xffffffffu, mx0, 2));
        mx1 = fmaxf(mx1, __shfl_xor_sync(0xffffffffu, mx1, 1));
        mx1 = fmaxf(mx1, __shfl_xor_sync(0xffffffffu, mx1, 2));
        float mn0 = fmaxf(m0, mx0), mn1 = fmaxf(m1, mx1);
        float al0 = __expf(m0 - mn0), al1 = __expf(m1 - mn1);
        m0 = mn0; m1 = mn1;
        float s0 = 0.0f, s1 = 0.0f;
#pragma unroll
        for (int nt = 0; nt < 8; nt++) {
            Sf[nt][0] = __expf(Sf[nt][0] - mn0); s0 += Sf[nt][0];
            Sf[nt][1] = __expf(Sf[nt][1] - mn0); s0 += Sf[nt][1];
            Sf[nt][2] = __expf(Sf[nt][2] - mn1); s1 += Sf[nt][2];
            Sf[nt][3] = __expf(Sf[nt][3] - mn1); s1 += Sf[nt][3];
        }
        s0 += __shfl_xor_sync(0xffffffffu, s0, 1);
        s0 += __shfl_xor_sync(0xffffffffu, s0, 2);
        s1 += __shfl_xor_sync(0xffffffffu, s1, 1);
        s1 += __shfl_xor_sync(0xffffffffu, s1, 2);
        l0 = l0 * al0 + s0;
        l1 = l1 * al1 + s1;
#pragma unroll
        for (int nt = 0; nt < 8; nt++) {
            Of[nt][0] *= al0; Of[nt][1] *= al0;
            Of[nt][2] *= al1; Of[nt][3] *= al1;
        }

#pragma unroll
        for (int nt = 0; nt < 8; nt++) {
            unsigned* p0 = &Pw[qr * KV_STRIDE + nt * 8 + 2 * qc];
            p0[0] = f2tf(Sf[nt][0]); p0[1] = f2tf(Sf[nt][1]);
            unsigned* p1 = &Pw[(qr + 8) * KV_STRIDE + nt * 8 + 2 * qc];
            p1[0] = f2tf(Sf[nt][2]); p1[1] = f2tf(Sf[nt][3]);
        }
        __syncwarp();

#pragma unroll
        for (int kt = 0; kt < 8; kt++) {
            unsigned a0 = Pw[qr * KV_STRIDE + kt * 8 + qc];
            unsigned a1 = Pw[(qr + 8) * KV_STRIDE + kt * 8 + qc];
            unsigned a2 = Pw[qr * KV_STRIDE + kt * 8 + qc + 4];
            unsigned a3 = Pw[(qr + 8) * KV_STRIDE + kt * 8 + qc + 4];
#pragma unroll
            for (int nt = 0; nt < 8; nt++) {
                unsigned b0 = Vt[(nt * 8 + qr) * KV_STRIDE + kt * 8 + qc];
                unsigned b1 = Vt[(nt * 8 + qr) * KV_STRIDE + kt * 8 + qc + 4];
                mma_tf32(Of[nt][0], Of[nt][1], Of[nt][2], Of[nt][3],
                         a0, a1, a2, a3, b0, b1);
            }
        }
    }

    // normalize + store O as tf32 to g_Otf [b*T+t][h*64+d]
    float il0 = 1.0f / l0, il1 = 1.0f / l1;
    int r0g = q0 + w * 16 + qr;
#pragma unroll
    for (int nt = 0; nt < 8; nt++) {
        int col = h * 64 + nt * 8 + 2 * qc;
        *(uint2*)&g_Otf[(b * TT + r0g) * CC + col] =
            make_uint2(f2tf(Of[nt][0] * il0), f2tf(Of[nt][1] * il0));
        *(uint2*)&g_Otf[(b * TT + r0g + 8) * CC + col] =
            make_uint2(f2tf(Of[nt][2] * il1), f2tf(Of[nt][3] * il1));
    }
}

// ---------------- kernel 3: output projection (tf32 mma, double-buffered) ---
__global__ __launch_bounds__(256) void out_proj_tc_k(
        const float* __restrict__ bo,
        float* __restrict__ out) {
    extern __shared__ unsigned smg[];
    unsigned* Xs = smg;
    unsigned* Ws = smg + 2 * 128 * XSTR;
    const int tid = threadIdx.x;
    const int w = tid >> 5, lane = tid & 31;
    const int qr = lane >> 2, qc = lane & 3;
    const int m0 = blockIdx.y * 128;
    const int n0 = blockIdx.x * 64;
    const int lrow = tid >> 1, lkb = (tid & 1) << 4;
    const int lkr = tid >> 3, lnb = (tid & 7) << 3;

    uint4 xr[4], wr[2];
#pragma unroll
    for (int q = 0; q < 4; q++)
        xr[q] = *(const uint4*)&g_Otf[(m0 + lrow) * CC + lkb + q * 4];
#pragma unroll
    for (int q = 0; q < 2; q++)
        wr[q] = *(const uint4*)&g_Wo[lkr * CC + n0 + lnb + q * 4];
    {
        unsigned* xd = &Xs[lrow * XSTR + lkb];
#pragma unroll
        for (int q = 0; q < 4; q++) *(uint4*)&xd[q * 4] = xr[q];
        unsigned* wd = &Ws[lkr * WSTR + lnb];
#pragma unroll
        for (int q = 0; q < 2; q++) *(uint4*)&wd[q * 4] = wr[q];
    }
    __syncthreads();

    float Cf[8][4] = {};
    const int NCH = CC / 32;
    for (int c = 0; c < NCH; c++) {
        if (c + 1 < NCH) {
            int k0 = (c + 1) * 32;
#pragma unroll
            for (int q = 0; q < 4; q++)
                xr[q] = *(const uint4*)&g_Otf[(m0 + lrow) * CC + k0 + lkb + q * 4];
#pragma unroll
            for (int q = 0; q < 2; q++)
                wr[q] = *(const uint4*)&g_Wo[(k0 + lkr) * CC + n0 + lnb + q * 4];
        }
        const unsigned* Xb = Xs + (c & 1) * 128 * XSTR;
        const unsigned* Wb = Ws + (c & 1) * 32 * WSTR;
#pragma unroll
        for (int kt = 0; kt < 4; kt++) {
            int abase = (w * 16 + qr) * XSTR + kt * 8 + qc;
            unsigned fa0 = Xb[abase];
            unsigned fa1 = Xb[abase + 8 * XSTR];
            unsigned fa2 = Xb[abase + 4];
            unsigned fa3 = Xb[abase + 8 * XSTR + 4];
            int bb0 = (kt * 8 + qc) * WSTR + qr;
            int bb1 = bb0 + 4 * WSTR;
#pragma unroll
            for (int nt = 0; nt < 8; nt++)
                mma_tf32(Cf[nt][0], Cf[nt][1], Cf[nt][2], Cf[nt][3],
                         fa0, fa1, fa2, fa3, Wb[bb0 + nt * 8], Wb[bb1 + nt * 8]);
        }
        if (c + 1 < NCH) {
            unsigned* Xn = Xs + ((c + 1) & 1) * 128 * XSTR;
            unsigned* Wn = Ws + ((c + 1) & 1) * 32 * WSTR;
            unsigned* xd = &Xn[lrow * XSTR + lkb];
#pragma unroll
            for (int q = 0; q < 4; q++) *(uint4*)&xd[q * 4] = xr[q];
            unsigned* wd = &Wn[lkr * WSTR + lnb];
#pragma unroll
            for (int q = 0; q < 2; q++) *(uint4*)&wd[q * 4] = wr[q];
            __syncthreads();
        }
    }

    const int r0 = m0 + w * 16 + qr;
#pragma unroll
    for (int nt = 0; nt < 8; nt++) {
        int n = n0 + nt * 8 + 2 * qc;
        float bv0 = bo[n], bv1 = bo[n + 1];
        *(float2*)&out[r0 * CC + n] =
            make_float2(Cf[nt][0] + bv0, Cf[nt][1] + bv1);
        *(float2*)&out[(r0 + 8) * CC + n] =
            make_float2(Cf[nt][2] + bv0, Cf[nt][3] + bv1);
    }
}

// ---------------- launcher ---------------------------------------------------
extern "C" void kernel_launch(void* const* d_in, const int* in_sizes, int n_in,
                              void* d_out, int out_size) {
    const float* x  = (const float*)d_in[0];
    const float* wq = (const float*)d_in[1];
    const float* bq = (const float*)d_in[2];
    const float* wk = (const float*)d_in[3];
    const float* bk = (const float*)d_in[4];
    const float* wv = (const float*)d_in[5];
    const float* bv = (const float*)d_in[6];
    const float* wo = (const float*)d_in[7];
    const float* bo = (const float*)d_in[8];
    float* out = (float*)d_out;

    cudaFuncSetAttribute(attn_k, cudaFuncAttributeMaxDynamicSharedMemorySize,
                         ATTN_SMEM_BYTES);
    cudaFuncSetAttribute(qkv_tc_k, cudaFuncAttributeMaxDynamicSharedMemorySize,
                         GEMM_SMEM_BYTES);
    cudaFuncSetAttribute(out_proj_tc_k,
                         cudaFuncAttributeMaxDynamicSharedMemorySize,
                         GEMM_SMEM_BYTES);

    pack_w_k<<<(CC * NQKV + 255) / 256, 256>>>(wq, wk, wv);
    pack_wo_k<<<(CC * CC + 255) / 256, 256>>>(wo);
    xconv_k<<<(BB * TT * CC + 255) / 256, 256>>>(x);
    rope_table_k<<<(TT * 32 + 255) / 256, 256>>>();
    qkv_tc_k<<<dim3(NQKV / 64, (BB * TT) / 128), 256, GEMM_SMEM_BYTES>>>(bq, bk, bv);
    attn_k<<<dim3(TT / 128, BB * HH), 256, ATTN_SMEM_BYTES>>>();
    out_proj_tc_k<<<dim3(CC / 64, (BB * TT) / 128), 256, GEMM_SMEM_BYTES>>>(bo, out);
}

// round 10
// speedup vs baseline: 2.7663x; 1.2127x over previous
#include <cuda_runtime.h>
#include <math.h>

#define BB 2
#define TT 2048
#define HH 12
#define DD 64
#define CC 768
#define NQKV 2304
#define NEG (-1e30f)

// ---------------- scratch (device globals; no allocations allowed) ----------
__device__ __align__(16) unsigned g_Wqkv[CC * NQKV];              // tf32 [K][N]
__device__ __align__(16) unsigned g_Wo[CC * CC];                  // tf32 [K][N]
__device__ __align__(16) unsigned g_Xtf[BB * TT * CC];            // tf32 x
__device__ __align__(16) unsigned g_QKVt[3 * BB * HH * TT * DD];  // tf32
__device__ __align__(16) unsigned g_Otf[BB * TT * CC];            // tf32 O
__device__ __align__(16) float    g_cos[TT * 32];
__device__ __align__(16) float    g_sin[TT * 32];

// ---------------- helpers ----------------------------------------------------
__device__ __forceinline__ unsigned f2tf(float f) {
    unsigned u;
    asm("cvt.rna.tf32.f32 %0, %1;" : "=r"(u) : "f"(f));
    return u;
}

__device__ __forceinline__ void mma_tf32(
        float& c0, float& c1, float& c2, float& c3,
        unsigned a0, unsigned a1, unsigned a2, unsigned a3,
        unsigned b0, unsigned b1) {
    asm("mma.sync.aligned.m16n8k8.row.col.f32.tf32.tf32.f32 "
        "{%0,%1,%2,%3}, {%4,%5,%6,%7}, {%8,%9}, {%0,%1,%2,%3};"
        : "+f"(c0), "+f"(c1), "+f"(c2), "+f"(c3)
        : "r"(a0), "r"(a1), "r"(a2), "r"(a3), "r"(b0), "r"(b1));
}

__device__ __forceinline__ void cp16(void* sdst, const void* gsrc) {
    unsigned s = (unsigned)__cvta_generic_to_shared(sdst);
    asm volatile("cp.async.cg.shared.global [%0], [%1], 16;" :: "r"(s), "l"(gsrc));
}
#define CP_COMMIT() asm volatile("cp.async.commit_group;")
#define CP_WAIT0()  asm volatile("cp.async.wait_group 0;")

// ---------------- kernel 0a: pack QKV weights (tf32) ------------------------
__global__ void pack_w_k(const float* __restrict__ wq,
                         const float* __restrict__ wk,
                         const float* __restrict__ wv) {
    int idx = blockIdx.x * 256 + threadIdx.x;
    if (idx >= CC * NQKV) return;
    int c = idx / NQKV, n = idx - c * NQKV;
    int which = n / 768, hd = n - which * 768;
    int h = hd >> 6, d = hd & 63;
    const float* w = (which == 0) ? wq : (which == 1) ? wk : wv;
    g_Wqkv[idx] = f2tf(w[(h * CC + c) * DD + d]);
}

// ---------------- kernel 0b: W_O pack ----------------------------------------
__global__ void pack_wo_k(const float* __restrict__ wo) {
    int idx = blockIdx.x * 256 + threadIdx.x;
    if (idx >= CC * CC) return;
    g_Wo[idx] = f2tf(wo[idx]);
}

// ---------------- kernel 0c: x -> tf32 ---------------------------------------
__global__ void xconv_k(const float* __restrict__ x) {
    int idx = blockIdx.x * 256 + threadIdx.x;
    if (idx >= BB * TT * CC) return;
    g_Xtf[idx] = f2tf(x[idx]);
}

// ---------------- kernel 0d: rope cos/sin table -----------------------------
__global__ void rope_table_k() {
    int idx = blockIdx.x * 256 + threadIdx.x;
    if (idx >= TT * 32) return;
    int t = idx >> 5, i = idx & 31;
    double e = (double)i * 0.41524101186092028;   // log2(10000)/32
    float inv = exp2f((float)(-e));
    float ang = (float)t * inv;
    float s, c;
    sincosf(ang, &s, &c);
    g_cos[idx] = c;
    g_sin[idx] = s;
}

// ---------------- tf32 GEMM: 128x64 tile, chunk 32, cp.async pipelined ------
#define XSTR 36
#define WSTR 72
#define GEMM_SMEM_UINTS (2 * 128 * XSTR + 2 * 32 * WSTR)
#define GEMM_SMEM_BYTES (GEMM_SMEM_UINTS * 4)

// ---------------- kernel 1: QKV GEMM + bias + RoPE (tf32 mma) ---------------
__global__ __launch_bounds__(256) void qkv_tc_k(
        const float* __restrict__ bq,
        const float* __restrict__ bk,
        const float* __restrict__ bv) {
    extern __shared__ unsigned smg[];
    unsigned* Xs = smg;                        // 2 * 128*36
    unsigned* Ws = smg + 2 * 128 * XSTR;       // 2 * 32*72
    const int tid = threadIdx.x;
    const int w = tid >> 5, lane = tid & 31;
    const int qr = lane >> 2, qc = lane & 3;
    const int m0 = blockIdx.y * 128;
    const int n0 = blockIdx.x * 64;
    const int lrow = tid >> 1, lkb = (tid & 1) << 4;   // X: row, 16 k
    const int lkr = tid >> 3, lnb = (tid & 7) << 3;    // W: k-row, 8 n

    // prologue: async-load chunk 0
    {
        unsigned* xd = &Xs[lrow * XSTR + lkb];
        const unsigned* xs = &g_Xtf[(m0 + lrow) * CC + lkb];
#pragma unroll
        for (int q = 0; q < 4; q++) cp16(xd + q * 4, xs + q * 4);
        unsigned* wd = &Ws[lkr * WSTR + lnb];
        const unsigned* ws = &g_Wqkv[lkr * NQKV + n0 + lnb];
#pragma unroll
        for (int q = 0; q < 2; q++) cp16(wd + q * 4, ws + q * 4);
        CP_COMMIT();
    }
    CP_WAIT0();
    __syncthreads();

    float Cf[8][4] = {};
    const int NCH = CC / 32;   // 24
    for (int c = 0; c < NCH; c++) {
        if (c + 1 < NCH) {
            int k0 = (c + 1) * 32;
            unsigned* Xn = Xs + ((c + 1) & 1) * 128 * XSTR;
            unsigned* Wn = Ws + ((c + 1) & 1) * 32 * WSTR;
            unsigned* xd = &Xn[lrow * XSTR + lkb];
            const unsigned* xs = &g_Xtf[(m0 + lrow) * CC + k0 + lkb];
#pragma unroll
            for (int q = 0; q < 4; q++) cp16(xd + q * 4, xs + q * 4);
            unsigned* wd = &Wn[lkr * WSTR + lnb];
            const unsigned* ws = &g_Wqkv[(k0 + lkr) * NQKV + n0 + lnb];
#pragma unroll
            for (int q = 0; q < 2; q++) cp16(wd + q * 4, ws + q * 4);
            CP_COMMIT();
        }
        const unsigned* Xb = Xs + (c & 1) * 128 * XSTR;
        const unsigned* Wb = Ws + (c & 1) * 32 * WSTR;
#pragma unroll
        for (int kt = 0; kt < 4; kt++) {
            int abase = (w * 16 + qr) * XSTR + kt * 8 + qc;
            unsigned fa0 = Xb[abase];
            unsigned fa1 = Xb[abase + 8 * XSTR];
            unsigned fa2 = Xb[abase + 4];
            unsigned fa3 = Xb[abase + 8 * XSTR + 4];
            int bb0 = (kt * 8 + qc) * WSTR + qr;
            int bb1 = bb0 + 4 * WSTR;
#pragma unroll
            for (int nt = 0; nt < 8; nt++)
                mma_tf32(Cf[nt][0], Cf[nt][1], Cf[nt][2], Cf[nt][3],
                         fa0, fa1, fa2, fa3, Wb[bb0 + nt * 8], Wb[bb1 + nt * 8]);
        }
        CP_WAIT0();
        __syncthreads();
    }

    // epilogue: bias + rope (+0.125 scale for Q) -> tf32 scatter to g_QKVt
    const int which = n0 / 768;
    const int h = (n0 % 768) >> 6;
    const float* bias = (which == 0) ? bq : (which == 1) ? bk : bv;
    const float qscale = (which == 0) ? 0.125f : 1.0f;
    const int r0 = m0 + w * 16 + qr;
#pragma unroll
    for (int nt = 0; nt < 8; nt++) {
        int d = nt * 8 + 2 * qc;
        float bv0 = bias[h * 64 + d], bv1 = bias[h * 64 + d + 1];
        int ii = nt * 4 + qc;
#pragma unroll
        for (int half = 0; half < 2; half++) {
            int r = r0 + half * 8;
            int bb = r >> 11, t = r & 2047;
            float v0 = Cf[nt][2 * half + 0] + bv0;
            float v1 = Cf[nt][2 * half + 1] + bv1;
            if (which < 2) {
                float cth = g_cos[t * 32 + ii];
                float sth = g_sin[t * 32 + ii];
                float nv0 = v0 * cth - v1 * sth;
                float nv1 = v0 * sth + v1 * cth;
                v0 = nv0 * qscale; v1 = nv1 * qscale;
            }
            *(uint2*)&g_QKVt[(((which * BB + bb) * HH + h) * TT + t) * DD + d] =
                make_uint2(f2tf(v0), f2tf(v1));
        }
    }
}

// ---------------- kernel 2: causal flash attention (tf32, cp.async) ---------
// Ks[2][64][68] natural [key][d]; Vs[2][64][72] natural [key][d]; Ps[8][16][68]
#define KSTR 68
#define VSTR 72
#define PSTR 68
#define ATTN_SMEM_UINTS (2 * 64 * KSTR + 2 * 64 * VSTR + 8 * 16 * PSTR)
#define ATTN_SMEM_BYTES (ATTN_SMEM_UINTS * 4)

__global__ __launch_bounds__(256) void attn_k() {
    extern __shared__ unsigned smu[];
    unsigned* Ks = smu;                          // 2 * 64*68
    unsigned* Vs = smu + 2 * 64 * KSTR;          // 2 * 64*72
    unsigned* Ps = Vs + 2 * 64 * VSTR;           // 8 * 16*68

    const int tid = threadIdx.x;
    const int w = tid >> 5, lane = tid & 31;
    const int qr = lane >> 2, qc = lane & 3;
    const int qi = (int)gridDim.x - 1 - (int)blockIdx.x; // heavy tiles first
    const int bh = blockIdx.y;
    const int b = bh / HH, h = bh % HH;
    const int q0 = qi * 128;

    const unsigned* Qg = g_QKVt + ((0 * BB + b) * HH + h) * TT * DD;
    const unsigned* Kg = g_QKVt + ((1 * BB + b) * HH + h) * TT * DD;
    const unsigned* Vg = g_QKVt + ((2 * BB + b) * HH + h) * TT * DD;

    // prologue: async-fill tile 0 into buffer 0
    {
#pragma unroll
        for (int i = 0; i < 4; i++) {
            int id = tid + 256 * i;
            int row = id >> 4, c16 = (id & 15) << 2;
            cp16(&Ks[row * KSTR + c16], &Kg[row * DD + c16]);
            cp16(&Vs[row * VSTR + c16], &Vg[row * DD + c16]);
        }
        CP_COMMIT();
    }

    // Q fragments (already tf32, pre-scaled)
    unsigned Qf[8][4];
    {
        const unsigned* qb = &Qg[(q0 + w * 16 + qr) * DD];
#pragma unroll
        for (int kt = 0; kt < 8; kt++) {
            Qf[kt][0] = qb[kt * 8 + qc];
            Qf[kt][1] = qb[8 * DD + kt * 8 + qc];
            Qf[kt][2] = qb[kt * 8 + qc + 4];
            Qf[kt][3] = qb[8 * DD + kt * 8 + qc + 4];
        }
    }

    float Of[8][4] = {};
    float m0 = NEG, m1 = NEG, l0 = 0.0f, l1 = 0.0f;
    unsigned* Pw = Ps + w * 16 * PSTR;

    CP_WAIT0();
    __syncthreads();

    const int njt = 2 * qi + 2;
    for (int j = 0; j < njt; j++) {
        // prefetch next tile into the other buffer
        if (j + 1 < njt) {
            unsigned* Kn = Ks + ((j + 1) & 1) * 64 * KSTR;
            unsigned* Vn = Vs + ((j + 1) & 1) * 64 * VSTR;
            const unsigned* ksrc = &Kg[(j + 1) * 64 * DD];
            const unsigned* vsrc = &Vg[(j + 1) * 64 * DD];
#pragma unroll
            for (int i = 0; i < 4; i++) {
                int id = tid + 256 * i;
                int row = id >> 4, c16 = (id & 15) << 2;
                cp16(&Kn[row * KSTR + c16], &ksrc[row * DD + c16]);
                cp16(&Vn[row * VSTR + c16], &vsrc[row * DD + c16]);
            }
            CP_COMMIT();
        }
        const unsigned* Kb = Ks + (j & 1) * 64 * KSTR;
        const unsigned* Vb = Vs + (j & 1) * 64 * VSTR;

        // S = Q K^T
        float Sf[8][4] = {};
#pragma unroll
        for (int nt = 0; nt < 8; nt++) {
#pragma unroll
            for (int kt = 0; kt < 8; kt++) {
                unsigned b0 = Kb[(nt * 8 + qr) * KSTR + kt * 8 + qc];
                unsigned b1 = Kb[(nt * 8 + qr) * KSTR + kt * 8 + qc + 4];
                mma_tf32(Sf[nt][0], Sf[nt][1], Sf[nt][2], Sf[nt][3],
                         Qf[kt][0], Qf[kt][1], Qf[kt][2], Qf[kt][3], b0, b1);
            }
        }

        if (j >= njt - 2) {
            int r0g = q0 + w * 16 + qr, r1g = r0g + 8;
#pragma unroll
            for (int nt = 0; nt < 8; nt++) {
                int c0g = j * 64 + nt * 8 + 2 * qc;
                if (c0g > r0g)     Sf[nt][0] = NEG;
                if (c0g + 1 > r0g) Sf[nt][1] = NEG;
                if (c0g > r1g)     Sf[nt][2] = NEG;
                if (c0g + 1 > r1g) Sf[nt][3] = NEG;
            }
        }

        // online softmax (quad of 4 lanes owns a row)
        float mx0 = NEG, mx1 = NEG;
#pragma unroll
        for (int nt = 0; nt < 8; nt++) {
            mx0 = fmaxf(mx0, fmaxf(Sf[nt][0], Sf[nt][1]));
            mx1 = fmaxf(mx1, fmaxf(Sf[nt][2], Sf[nt][3]));
        }
        mx0 = fmaxf(mx0, __shfl_xor_sync(0xffffffffu, mx0, 1));
        mx0 = fmaxf(mx0, __shfl_xor_sync(0xffffffffu, mx0, 2));
        mx1 = fmaxf(mx1, __shfl_xor_sync(0xffffffffu, mx1, 1));
        mx1 = fmaxf(mx1, __shfl_xor_sync(0xffffffffu, mx1, 2));
        float mn0 = fmaxf(m0, mx0), mn1 = fmaxf(m1, mx1);
        float al0 = __expf(m0 - mn0), al1 = __expf(m1 - mn1);
        m0 = mn0; m1 = mn1;
        float s0 = 0.0f, s1 = 0.0f;
#pragma unroll
        for (int nt = 0; nt < 8; nt++) {
            Sf[nt][0] = __expf(Sf[nt][0] - mn0); s0 += Sf[nt][0];
            Sf[nt][1] = __expf(Sf[nt][1] - mn0); s0 += Sf[nt][1];
            Sf[nt][2] = __expf(Sf[nt][2] - mn1); s1 += Sf[nt][2];
            Sf[nt][3] = __expf(Sf[nt][3] - mn1); s1 += Sf[nt][3];
        }
        s0 += __shfl_xor_sync(0xffffffffu, s0, 1);
        s0 += __shfl_xor_sync(0xffffffffu, s0, 2);
        s1 += __shfl_xor_sync(0xffffffffu, s1, 1);
        s1 += __shfl_xor_sync(0xffffffffu, s1, 2);
        l0 = l0 * al0 + s0;
        l1 = l1 * al1 + s1;
#pragma unroll
        for (int nt = 0; nt < 8; nt++) {
            Of[nt][0] *= al0; Of[nt][1] *= al0;
            Of[nt][2] *= al1; Of[nt][3] *= al1;
        }

        // P (tf32) to per-warp smem
#pragma unroll
        for (int nt = 0; nt < 8; nt++) {
            unsigned* p0 = &Pw[qr * PSTR + nt * 8 + 2 * qc];
            p0[0] = f2tf(Sf[nt][0]); p0[1] = f2tf(Sf[nt][1]);
            unsigned* p1 = &Pw[(qr + 8) * PSTR + nt * 8 + 2 * qc];
            p1[0] = f2tf(Sf[nt][2]); p1[1] = f2tf(Sf[nt][3]);
        }
        __syncwarp();

        // O += P V
#pragma unroll
        for (int kt = 0; kt < 8; kt++) {
            unsigned a0 = Pw[qr * PSTR + kt * 8 + qc];
            unsigned a1 = Pw[(qr + 8) * PSTR + kt * 8 + qc];
            unsigned a2 = Pw[qr * PSTR + kt * 8 + qc + 4];
            unsigned a3 = Pw[(qr + 8) * PSTR + kt * 8 + qc + 4];
#pragma unroll
            for (int nt = 0; nt < 8; nt++) {
                unsigned b0 = Vb[(kt * 8 + qc) * VSTR + nt * 8 + qr];
                unsigned b1 = Vb[(kt * 8 + qc + 4) * VSTR + nt * 8 + qr];
                mma_tf32(Of[nt][0], Of[nt][1], Of[nt][2], Of[nt][3],
                         a0, a1, a2, a3, b0, b1);
            }
        }

        CP_WAIT0();
        __syncthreads();
    }

    // normalize + store O as tf32
    float il0 = 1.0f / l0, il1 = 1.0f / l1;
    int r0g = q0 + w * 16 + qr;
#pragma unroll
    for (int nt = 0; nt < 8; nt++) {
        int col = h * 64 + nt * 8 + 2 * qc;
        *(uint2*)&g_Otf[(b * TT + r0g) * CC + col] =
            make_uint2(f2tf(Of[nt][0] * il0), f2tf(Of[nt][1] * il0));
        *(uint2*)&g_Otf[(b * TT + r0g + 8) * CC + col] =
            make_uint2(f2tf(Of[nt][2] * il1), f2tf(Of[nt][3] * il1));
    }
}

// ---------------- kernel 3: output projection (tf32 mma, cp.async) ----------
__global__ __launch_bounds__(256) void out_proj_tc_k(
        const float* __restrict__ bo,
        float* __restrict__ out) {
    extern __shared__ unsigned smg[];
    unsigned* Xs = smg;
    unsigned* Ws = smg + 2 * 128 * XSTR;
    const int tid = threadIdx.x;
    const int w = tid >> 5, lane = tid & 31;
    const int qr = lane >> 2, qc = lane & 3;
    const int m0 = blockIdx.y * 128;
    const int n0 = blockIdx.x * 64;
    const int lrow = tid >> 1, lkb = (tid & 1) << 4;
    const int lkr = tid >> 3, lnb = (tid & 7) << 3;

    {
        unsigned* xd = &Xs[lrow * XSTR + lkb];
        const unsigned* xs = &g_Otf[(m0 + lrow) * CC + lkb];
#pragma unroll
        for (int q = 0; q < 4; q++) cp16(xd + q * 4, xs + q * 4);
        unsigned* wd = &Ws[lkr * WSTR + lnb];
        const unsigned* ws = &g_Wo[lkr * CC + n0 + lnb];
#pragma unroll
        for (int q = 0; q < 2; q++) cp16(wd + q * 4, ws + q * 4);
        CP_COMMIT();
    }
    CP_WAIT0();
    __syncthreads();

    float Cf[8][4] = {};
    const int NCH = CC / 32;
    for (int c = 0; c < NCH; c++) {
        if (c + 1 < NCH) {
            int k0 = (c + 1) * 32;
            unsigned* Xn = Xs + ((c + 1) & 1) * 128 * XSTR;
            unsigned* Wn = Ws + ((c + 1) & 1) * 32 * WSTR;
            unsigned* xd = &Xn[lrow * XSTR + lkb];
            const unsigned* xs = &g_Otf[(m0 + lrow) * CC + k0 + lkb];
#pragma unroll
            for (int q = 0; q < 4; q++) cp16(xd + q * 4, xs + q * 4);
            unsigned* wd = &Wn[lkr * WSTR + lnb];
            const unsigned* ws = &g_Wo[(k0 + lkr) * CC + n0 + lnb];
#pragma unroll
            for (int q = 0; q < 2; q++) cp16(wd + q * 4, ws + q * 4);
            CP_COMMIT();
        }
        const unsigned* Xb = Xs + (c & 1) * 128 * XSTR;
        const unsigned* Wb = Ws + (c & 1) * 32 * WSTR;
#pragma unroll
        for (int kt = 0; kt < 4; kt++) {
            int abase = (w * 16 + qr) * XSTR + kt * 8 + qc;
            unsigned fa0 = Xb[abase];
            unsigned fa1 = Xb[abase + 8 * XSTR];
            unsigned fa2 = Xb[abase + 4];
            unsigned fa3 = Xb[abase + 8 * XSTR + 4];
            int bb0 = (kt * 8 + qc) * WSTR + qr;
            int bb1 = bb0 + 4 * WSTR;
#pragma unroll
            for (int nt = 0; nt < 8; nt++)
                mma_tf32(Cf[nt][0], Cf[nt][1], Cf[nt][2], Cf[nt][3],
                         fa0, fa1, fa2, fa3, Wb[bb0 + nt * 8], Wb[bb1 + nt * 8]);
        }
        CP_WAIT0();
        __syncthreads();
    }

    const int r0 = m0 + w * 16 + qr;
#pragma unroll
    for (int nt = 0; nt < 8; nt++) {
        int n = n0 + nt * 8 + 2 * qc;
        float bv0 = bo[n], bv1 = bo[n + 1];
        *(float2*)&out[r0 * CC + n] =
            make_float2(Cf[nt][0] + bv0, Cf[nt][1] + bv1);
        *(float2*)&out[(r0 + 8) * CC + n] =
            make_float2(Cf[nt][2] + bv0, Cf[nt][3] + bv1);
    }
}

// ---------------- launcher ---------------------------------------------------
extern "C" void kernel_launch(void* const* d_in, const int* in_sizes, int n_in,
                              void* d_out, int out_size) {
    const float* x  = (const float*)d_in[0];
    const float* wq = (const float*)d_in[1];
    const float* bq = (const float*)d_in[2];
    const float* wk = (const float*)d_in[3];
    const float* bk = (const float*)d_in[4];
    const float* wv = (const float*)d_in[5];
    const float* bv = (const float*)d_in[6];
    const float* wo = (const float*)d_in[7];
    const float* bo = (const float*)d_in[8];
    float* out = (float*)d_out;

    cudaFuncSetAttribute(attn_k, cudaFuncAttributeMaxDynamicSharedMemorySize,
                         ATTN_SMEM_BYTES);
    cudaFuncSetAttribute(qkv_tc_k, cudaFuncAttributeMaxDynamicSharedMemorySize,
                         GEMM_SMEM_BYTES);
    cudaFuncSetAttribute(out_proj_tc_k,
                         cudaFuncAttributeMaxDynamicSharedMemorySize,
                         GEMM_SMEM_BYTES);

    pack_w_k<<<(CC * NQKV + 255) / 256, 256>>>(wq, wk, wv);
    pack_wo_k<<<(CC * CC + 255) / 256, 256>>>(wo);
    xconv_k<<<(BB * TT * CC + 255) / 256, 256>>>(x);
    rope_table_k<<<(TT * 32 + 255) / 256, 256>>>();
    qkv_tc_k<<<dim3(NQKV / 64, (BB * TT) / 128), 256, GEMM_SMEM_BYTES>>>(bq, bk, bv);
    attn_k<<<dim3(TT / 128, BB * HH), 256, ATTN_SMEM_BYTES>>>();
    out_proj_tc_k<<<dim3(CC / 64, (BB * TT) / 128), 256, GEMM_SMEM_BYTES>>>(bo, out);
}

// round 11
// speedup vs baseline: 3.0622x; 1.1070x over previous
#include <cuda_runtime.h>
#include <math.h>

#define BB 2
#define TT 2048
#define HH 12
#define DD 64
#define CC 768
#define NQKV 2304
#define NEG (-1e30f)

// ---------------- scratch (device globals; no allocations allowed) ----------
__device__ __align__(16) unsigned g_Wqkv[CC * NQKV];              // tf32 [K][N]
__device__ __align__(16) unsigned g_Wo[CC * CC];                  // tf32 [K][N]
__device__ __align__(16) unsigned g_Xtf[BB * TT * CC];            // tf32 x
__device__ __align__(16) unsigned g_QKVt[3 * BB * HH * TT * DD];  // tf32
__device__ __align__(16) unsigned g_Otf[BB * TT * CC];            // tf32 O
__device__ __align__(16) float    g_cos[TT * 32];
__device__ __align__(16) float    g_sin[TT * 32];
// split-attention partials (rows t>=1024 only are used)
__device__ __align__(16) float    g_Op[2][BB * TT * CC];          // unnormalized O
__device__ __align__(16) float    g_m[2][BB * HH * TT];
__device__ __align__(16) float    g_l[2][BB * HH * TT];

// ---------------- helpers ----------------------------------------------------
__device__ __forceinline__ unsigned f2tf(float f) {
    unsigned u;
    asm("cvt.rna.tf32.f32 %0, %1;" : "=r"(u) : "f"(f));
    return u;
}

__device__ __forceinline__ void mma_tf32(
        float& c0, float& c1, float& c2, float& c3,
        unsigned a0, unsigned a1, unsigned a2, unsigned a3,
        unsigned b0, unsigned b1) {
    asm("mma.sync.aligned.m16n8k8.row.col.f32.tf32.tf32.f32 "
        "{%0,%1,%2,%3}, {%4,%5,%6,%7}, {%8,%9}, {%0,%1,%2,%3};"
        : "+f"(c0), "+f"(c1), "+f"(c2), "+f"(c3)
        : "r"(a0), "r"(a1), "r"(a2), "r"(a3), "r"(b0), "r"(b1));
}

__device__ __forceinline__ void cp16(void* sdst, const void* gsrc) {
    unsigned s = (unsigned)__cvta_generic_to_shared(sdst);
    asm volatile("cp.async.cg.shared.global [%0], [%1], 16;" :: "r"(s), "l"(gsrc));
}
#define CP_COMMIT() asm volatile("cp.async.commit_group;")
#define CP_WAIT0()  asm volatile("cp.async.wait_group 0;")

// ---------------- kernel 0a: pack QKV weights (tf32) ------------------------
__global__ void pack_w_k(const float* __restrict__ wq,
                         const float* __restrict__ wk,
                         const float* __restrict__ wv) {
    int idx = blockIdx.x * 256 + threadIdx.x;
    if (idx >= CC * NQKV) return;
    int c = idx / NQKV, n = idx - c * NQKV;
    int which = n / 768, hd = n - which * 768;
    int h = hd >> 6, d = hd & 63;
    const float* w = (which == 0) ? wq : (which == 1) ? wk : wv;
    g_Wqkv[idx] = f2tf(w[(h * CC + c) * DD + d]);
}

// ---------------- kernel 0b: W_O pack ----------------------------------------
__global__ void pack_wo_k(const float* __restrict__ wo) {
    int idx = blockIdx.x * 256 + threadIdx.x;
    if (idx >= CC * CC) return;
    g_Wo[idx] = f2tf(wo[idx]);
}

// ---------------- kernel 0c: x -> tf32 ---------------------------------------
__global__ void xconv_k(const float* __restrict__ x) {
    int idx = blockIdx.x * 256 + threadIdx.x;
    if (idx >= BB * TT * CC) return;
    g_Xtf[idx] = f2tf(x[idx]);
}

// ---------------- kernel 0d: rope cos/sin table -----------------------------
__global__ void rope_table_k() {
    int idx = blockIdx.x * 256 + threadIdx.x;
    if (idx >= TT * 32) return;
    int t = idx >> 5, i = idx & 31;
    double e = (double)i * 0.41524101186092028;   // log2(10000)/32
    float inv = exp2f((float)(-e));
    float ang = (float)t * inv;
    float s, c;
    sincosf(ang, &s, &c);
    g_cos[idx] = c;
    g_sin[idx] = s;
}

// ---------------- tf32 GEMM: 128x64 tile, chunk 32, cp.async pipelined ------
#define XSTR 36
#define WSTR 72
#define GEMM_SMEM_UINTS (2 * 128 * XSTR + 2 * 32 * WSTR)
#define GEMM_SMEM_BYTES (GEMM_SMEM_UINTS * 4)

// ---------------- kernel 1: QKV GEMM + bias + RoPE (tf32 mma) ---------------
__global__ __launch_bounds__(256, 3) void qkv_tc_k(
        const float* __restrict__ bq,
        const float* __restrict__ bk,
        const float* __restrict__ bv) {
    extern __shared__ unsigned smg[];
    unsigned* Xs = smg;                        // 2 * 128*36
    unsigned* Ws = smg + 2 * 128 * XSTR;       // 2 * 32*72
    const int tid = threadIdx.x;
    const int w = tid >> 5, lane = tid & 31;
    const int qr = lane >> 2, qc = lane & 3;
    const int m0 = blockIdx.y * 128;
    const int n0 = blockIdx.x * 64;
    const int lrow = tid >> 1, lkb = (tid & 1) << 4;   // X: row, 16 k
    const int lkr = tid >> 3, lnb = (tid & 7) << 3;    // W: k-row, 8 n

    // prologue: async-load chunk 0
    {
        unsigned* xd = &Xs[lrow * XSTR + lkb];
        const unsigned* xs = &g_Xtf[(m0 + lrow) * CC + lkb];
#pragma unroll
        for (int q = 0; q < 4; q++) cp16(xd + q * 4, xs + q * 4);
        unsigned* wd = &Ws[lkr * WSTR + lnb];
        const unsigned* ws = &g_Wqkv[lkr * NQKV + n0 + lnb];
#pragma unroll
        for (int q = 0; q < 2; q++) cp16(wd + q * 4, ws + q * 4);
        CP_COMMIT();
    }
    CP_WAIT0();
    __syncthreads();

    float Cf[8][4] = {};
    const int NCH = CC / 32;   // 24
    for (int c = 0; c < NCH; c++) {
        if (c + 1 < NCH) {
            int k0 = (c + 1) * 32;
            unsigned* Xn = Xs + ((c + 1) & 1) * 128 * XSTR;
            unsigned* Wn = Ws + ((c + 1) & 1) * 32 * WSTR;
            unsigned* xd = &Xn[lrow * XSTR + lkb];
            const unsigned* xs = &g_Xtf[(m0 + lrow) * CC + k0 + lkb];
#pragma unroll
            for (int q = 0; q < 4; q++) cp16(xd + q * 4, xs + q * 4);
            unsigned* wd = &Wn[lkr * WSTR + lnb];
            const unsigned* ws = &g_Wqkv[(k0 + lkr) * NQKV + n0 + lnb];
#pragma unroll
            for (int q = 0; q < 2; q++) cp16(wd + q * 4, ws + q * 4);
            CP_COMMIT();
        }
        const unsigned* Xb = Xs + (c & 1) * 128 * XSTR;
        const unsigned* Wb = Ws + (c & 1) * 32 * WSTR;
#pragma unroll
        for (int kt = 0; kt < 4; kt++) {
            int abase = (w * 16 + qr) * XSTR + kt * 8 + qc;
            unsigned fa0 = Xb[abase];
            unsigned fa1 = Xb[abase + 8 * XSTR];
            unsigned fa2 = Xb[abase + 4];
            unsigned fa3 = Xb[abase + 8 * XSTR + 4];
            int bb0 = (kt * 8 + qc) * WSTR + qr;
            int bb1 = bb0 + 4 * WSTR;
#pragma unroll
            for (int nt = 0; nt < 8; nt++)
                mma_tf32(Cf[nt][0], Cf[nt][1], Cf[nt][2], Cf[nt][3],
                         fa0, fa1, fa2, fa3, Wb[bb0 + nt * 8], Wb[bb1 + nt * 8]);
        }
        CP_WAIT0();
        __syncthreads();
    }

    // epilogue: bias + rope (+0.125 scale for Q) -> tf32 scatter to g_QKVt
    const int which = n0 / 768;
    const int h = (n0 % 768) >> 6;
    const float* bias = (which == 0) ? bq : (which == 1) ? bk : bv;
    const float qscale = (which == 0) ? 0.125f : 1.0f;
    const int r0 = m0 + w * 16 + qr;
#pragma unroll
    for (int nt = 0; nt < 8; nt++) {
        int d = nt * 8 + 2 * qc;
        float bv0 = bias[h * 64 + d], bv1 = bias[h * 64 + d + 1];
        int ii = nt * 4 + qc;
#pragma unroll
        for (int half = 0; half < 2; half++) {
            int r = r0 + half * 8;
            int bb = r >> 11, t = r & 2047;
            float v0 = Cf[nt][2 * half + 0] + bv0;
            float v1 = Cf[nt][2 * half + 1] + bv1;
            if (which < 2) {
                float cth = g_cos[t * 32 + ii];
                float sth = g_sin[t * 32 + ii];
                float nv0 = v0 * cth - v1 * sth;
                float nv1 = v0 * sth + v1 * cth;
                v0 = nv0 * qscale; v1 = nv1 * qscale;
            }
            *(uint2*)&g_QKVt[(((which * BB + bb) * HH + h) * TT + t) * DD + d] =
                make_uint2(f2tf(v0), f2tf(v1));
        }
    }
}

// ---------------- kernel 2: causal flash attention (tf32, split-K balanced) -
// grid = (BB*HH, 24).  by<16: split block (qi = 15 - by/2, half 'part');
// by>=16: unsplit (qi = 23 - by).  Heavy slots launch first (x-fastest order).
#define KSTR 68
#define VSTR 72
#define PSTR 68
#define ATTN_SMEM_UINTS (2 * 64 * KSTR + 2 * 64 * VSTR + 8 * 16 * PSTR)
#define ATTN_SMEM_BYTES (ATTN_SMEM_UINTS * 4)

__global__ __launch_bounds__(256) void attn_k() {
    extern __shared__ unsigned smu[];
    unsigned* Ks = smu;                          // 2 * 64*68
    unsigned* Vs = smu + 2 * 64 * KSTR;          // 2 * 64*72
    unsigned* Ps = Vs + 2 * 64 * VSTR;           // 8 * 16*68

    const int tid = threadIdx.x;
    const int w = tid >> 5, lane = tid & 31;
    const int qr = lane >> 2, qc = lane & 3;

    const int by = blockIdx.y;
    int qi, part, nparts;
    if (by < 16) { qi = 15 - (by >> 1); part = by & 1; nparts = 2; }
    else         { qi = 23 - by;        part = 0;      nparts = 1; }
    const int bh = blockIdx.x;
    const int b = bh / HH, h = bh % HH;
    const int q0 = qi * 128;
    const int njt = 2 * qi + 2;
    const int jn = (nparts == 2) ? (qi + 1) : njt;
    const int j0 = part * jn;

    const unsigned* Qg = g_QKVt + ((0 * BB + b) * HH + h) * TT * DD;
    const unsigned* Kg = g_QKVt + ((1 * BB + b) * HH + h) * TT * DD;
    const unsigned* Vg = g_QKVt + ((2 * BB + b) * HH + h) * TT * DD;

    // prologue: async-fill tile j0 into buffer (j0&1)
    {
        unsigned* K0 = Ks + (j0 & 1) * 64 * KSTR;
        unsigned* V0 = Vs + (j0 & 1) * 64 * VSTR;
        const unsigned* ksrc = &Kg[j0 * 64 * DD];
        const unsigned* vsrc = &Vg[j0 * 64 * DD];
#pragma unroll
        for (int i = 0; i < 4; i++) {
            int id = tid + 256 * i;
            int row = id >> 4, c16 = (id & 15) << 2;
            cp16(&K0[row * KSTR + c16], &ksrc[row * DD + c16]);
            cp16(&V0[row * VSTR + c16], &vsrc[row * DD + c16]);
        }
        CP_COMMIT();
    }

    // Q fragments (already tf32, pre-scaled)
    unsigned Qf[8][4];
    {
        const unsigned* qb = &Qg[(q0 + w * 16 + qr) * DD];
#pragma unroll
        for (int kt = 0; kt < 8; kt++) {
            Qf[kt][0] = qb[kt * 8 + qc];
            Qf[kt][1] = qb[8 * DD + kt * 8 + qc];
            Qf[kt][2] = qb[kt * 8 + qc + 4];
            Qf[kt][3] = qb[8 * DD + kt * 8 + qc + 4];
        }
    }

    float Of[8][4] = {};
    float m0 = NEG, m1 = NEG, l0 = 0.0f, l1 = 0.0f;
    unsigned* Pw = Ps + w * 16 * PSTR;

    CP_WAIT0();
    __syncthreads();

    const int jend = j0 + jn;
    for (int j = j0; j < jend; j++) {
        // prefetch next tile into the other buffer
        if (j + 1 < jend) {
            unsigned* Kn = Ks + ((j + 1) & 1) * 64 * KSTR;
            unsigned* Vn = Vs + ((j + 1) & 1) * 64 * VSTR;
            const unsigned* ksrc = &Kg[(j + 1) * 64 * DD];
            const unsigned* vsrc = &Vg[(j + 1) * 64 * DD];
#pragma unroll
            for (int i = 0; i < 4; i++) {
                int id = tid + 256 * i;
                int row = id >> 4, c16 = (id & 15) << 2;
                cp16(&Kn[row * KSTR + c16], &ksrc[row * DD + c16]);
                cp16(&Vn[row * VSTR + c16], &vsrc[row * DD + c16]);
            }
            CP_COMMIT();
        }
        const unsigned* Kb = Ks + (j & 1) * 64 * KSTR;
        const unsigned* Vb = Vs + (j & 1) * 64 * VSTR;

        // S = Q K^T
        float Sf[8][4] = {};
#pragma unroll
        for (int nt = 0; nt < 8; nt++) {
#pragma unroll
            for (int kt = 0; kt < 8; kt++) {
                unsigned b0 = Kb[(nt * 8 + qr) * KSTR + kt * 8 + qc];
                unsigned b1 = Kb[(nt * 8 + qr) * KSTR + kt * 8 + qc + 4];
                mma_tf32(Sf[nt][0], Sf[nt][1], Sf[nt][2], Sf[nt][3],
                         Qf[kt][0], Qf[kt][1], Qf[kt][2], Qf[kt][3], b0, b1);
            }
        }

        if (j >= njt - 2) {   // global diagonal tiles
            int r0g = q0 + w * 16 + qr, r1g = r0g + 8;
#pragma unroll
            for (int nt = 0; nt < 8; nt++) {
                int c0g = j * 64 + nt * 8 + 2 * qc;
                if (c0g > r0g)     Sf[nt][0] = NEG;
                if (c0g + 1 > r0g) Sf[nt][1] = NEG;
                if (c0g > r1g)     Sf[nt][2] = NEG;
                if (c0g + 1 > r1g) Sf[nt][3] = NEG;
            }
        }

        // online softmax (quad of 4 lanes owns a row)
        float mx0 = NEG, mx1 = NEG;
#pragma unroll
        for (int nt = 0; nt < 8; nt++) {
            mx0 = fmaxf(mx0, fmaxf(Sf[nt][0], Sf[nt][1]));
            mx1 = fmaxf(mx1, fmaxf(Sf[nt][2], Sf[nt][3]));
        }
        mx0 = fmaxf(mx0, __shfl_xor_sync(0xffffffffu, mx0, 1));
        mx0 = fmaxf(mx0, __shfl_xor_sync(0xffffffffu, mx0, 2));
        mx1 = fmaxf(mx1, __shfl_xor_sync(0xffffffffu, mx1, 1));
        mx1 = fmaxf(mx1, __shfl_xor_sync(0xffffffffu, mx1, 2));
        float mn0 = fmaxf(m0, mx0), mn1 = fmaxf(m1, mx1);
        float al0 = __expf(m0 - mn0), al1 = __expf(m1 - mn1);
        m0 = mn0; m1 = mn1;
        float s0 = 0.0f, s1 = 0.0f;
#pragma unroll
        for (int nt = 0; nt < 8; nt++) {
            Sf[nt][0] = __expf(Sf[nt][0] - mn0); s0 += Sf[nt][0];
            Sf[nt][1] = __expf(Sf[nt][1] - mn0); s0 += Sf[nt][1];
            Sf[nt][2] = __expf(Sf[nt][2] - mn1); s1 += Sf[nt][2];
            Sf[nt][3] = __expf(Sf[nt][3] - mn1); s1 += Sf[nt][3];
        }
        s0 += __shfl_xor_sync(0xffffffffu, s0, 1);
        s0 += __shfl_xor_sync(0xffffffffu, s0, 2);
        s1 += __shfl_xor_sync(0xffffffffu, s1, 1);
        s1 += __shfl_xor_sync(0xffffffffu, s1, 2);
        l0 = l0 * al0 + s0;
        l1 = l1 * al1 + s1;
#pragma unroll
        for (int nt = 0; nt < 8; nt++) {
            Of[nt][0] *= al0; Of[nt][1] *= al0;
            Of[nt][2] *= al1; Of[nt][3] *= al1;
        }

        // P (tf32) to per-warp smem
#pragma unroll
        for (int nt = 0; nt < 8; nt++) {
            unsigned* p0 = &Pw[qr * PSTR + nt * 8 + 2 * qc];
            p0[0] = f2tf(Sf[nt][0]); p0[1] = f2tf(Sf[nt][1]);
            unsigned* p1 = &Pw[(qr + 8) * PSTR + nt * 8 + 2 * qc];
            p1[0] = f2tf(Sf[nt][2]); p1[1] = f2tf(Sf[nt][3]);
        }
        __syncwarp();

        // O += P V
#pragma unroll
        for (int kt = 0; kt < 8; kt++) {
            unsigned a0 = Pw[qr * PSTR + kt * 8 + qc];
            unsigned a1 = Pw[(qr + 8) * PSTR + kt * 8 + qc];
            unsigned a2 = Pw[qr * PSTR + kt * 8 + qc + 4];
            unsigned a3 = Pw[(qr + 8) * PSTR + kt * 8 + qc + 4];
#pragma unroll
            for (int nt = 0; nt < 8; nt++) {
                unsigned b0 = Vb[(kt * 8 + qc) * VSTR + nt * 8 + qr];
                unsigned b1 = Vb[(kt * 8 + qc + 4) * VSTR + nt * 8 + qr];
                mma_tf32(Of[nt][0], Of[nt][1], Of[nt][2], Of[nt][3],
                         a0, a1, a2, a3, b0, b1);
            }
        }

        CP_WAIT0();
        __syncthreads();
    }

    int r0g = q0 + w * 16 + qr;
    if (nparts == 1) {
        // normalize + store O as tf32
        float il0 = 1.0f / l0, il1 = 1.0f / l1;
#pragma unroll
        for (int nt = 0; nt < 8; nt++) {
            int col = h * 64 + nt * 8 + 2 * qc;
            *(uint2*)&g_Otf[(b * TT + r0g) * CC + col] =
                make_uint2(f2tf(Of[nt][0] * il0), f2tf(Of[nt][1] * il0));
            *(uint2*)&g_Otf[(b * TT + r0g + 8) * CC + col] =
                make_uint2(f2tf(Of[nt][2] * il1), f2tf(Of[nt][3] * il1));
        }
    } else {
        // store unnormalized fp32 partials + (m, l)
        float* Op = g_Op[part];
#pragma unroll
        for (int nt = 0; nt < 8; nt++) {
            int col = h * 64 + nt * 8 + 2 * qc;
            *(float2*)&Op[(b * TT + r0g) * CC + col] =
                make_float2(Of[nt][0], Of[nt][1]);
            *(float2*)&Op[(b * TT + r0g + 8) * CC + col] =
                make_float2(Of[nt][2], Of[nt][3]);
        }
        if (qc == 0) {
            int mlrow = (b * HH + h) * TT + r0g;
            g_m[part][mlrow] = m0;     g_l[part][mlrow] = l0;
            g_m[part][mlrow + 8] = m1; g_l[part][mlrow + 8] = l1;
        }
    }
}

// ---------------- kernel 2b: merge split-attention partials (t >= 1024) -----
__global__ void attn_merge_k() {
    int idx = blockIdx.x * 256 + threadIdx.x;
    const int total = BB * 1024 * CC;
    if (idx >= total) return;
    int b = idx / (1024 * CC);
    int rem = idx - b * 1024 * CC;
    int t = 1024 + rem / CC;
    int c = rem % CC;
    int h = c >> 6;
    int mlrow = (b * HH + h) * TT + t;
    float m1 = g_m[0][mlrow], m2 = g_m[1][mlrow];
    float l1 = g_l[0][mlrow], l2 = g_l[1][mlrow];
    float m = fmaxf(m1, m2);
    float a1 = __expf(m1 - m), a2 = __expf(m2 - m);
    float l = a1 * l1 + a2 * l2;
    int oidx = (b * TT + t) * CC + c;
    float o = (a1 * g_Op[0][oidx] + a2 * g_Op[1][oidx]) / l;
    g_Otf[oidx] = f2tf(o);
}

// ---------------- kernel 3: output projection (tf32 mma, cp.async) ----------
__global__ __launch_bounds__(256, 3) void out_proj_tc_k(
        const float* __restrict__ bo,
        float* __restrict__ out) {
    extern __shared__ unsigned smg[];
    unsigned* Xs = smg;
    unsigned* Ws = smg + 2 * 128 * XSTR;
    const int tid = threadIdx.x;
    const int w = tid >> 5, lane = tid & 31;
    const int qr = lane >> 2, qc = lane & 3;
    const int m0 = blockIdx.y * 128;
    const int n0 = blockIdx.x * 64;
    const int lrow = tid >> 1, lkb = (tid & 1) << 4;
    const int lkr = tid >> 3, lnb = (tid & 7) << 3;

    {
        unsigned* xd = &Xs[lrow * XSTR + lkb];
        const unsigned* xs = &g_Otf[(m0 + lrow) * CC + lkb];
#pragma unroll
        for (int q = 0; q < 4; q++) cp16(xd + q * 4, xs + q * 4);
        unsigned* wd = &Ws[lkr * WSTR + lnb];
        const unsigned* ws = &g_Wo[lkr * CC + n0 + lnb];
#pragma unroll
        for (int q = 0; q < 2; q++) cp16(wd + q * 4, ws + q * 4);
        CP_COMMIT();
    }
    CP_WAIT0();
    __syncthreads();

    float Cf[8][4] = {};
    const int NCH = CC / 32;
    for (int c = 0; c < NCH; c++) {
        if (c + 1 < NCH) {
            int k0 = (c + 1) * 32;
            unsigned* Xn = Xs + ((c + 1) & 1) * 128 * XSTR;
            unsigned* Wn = Ws + ((c + 1) & 1) * 32 * WSTR;
            unsigned* xd = &Xn[lrow * XSTR + lkb];
            const unsigned* xs = &g_Otf[(m0 + lrow) * CC + k0 + lkb];
#pragma unroll
            for (int q = 0; q < 4; q++) cp16(xd + q * 4, xs + q * 4);
            unsigned* wd = &Wn[lkr * WSTR + lnb];
            const unsigned* ws = &g_Wo[(k0 + lkr) * CC + n0 + lnb];
#pragma unroll
            for (int q = 0; q < 2; q++) cp16(wd + q * 4, ws + q * 4);
            CP_COMMIT();
        }
        const unsigned* Xb = Xs + (c & 1) * 128 * XSTR;
        const unsigned* Wb = Ws + (c & 1) * 32 * WSTR;
#pragma unroll
        for (int kt = 0; kt < 4; kt++) {
            int abase = (w * 16 + qr) * XSTR + kt * 8 + qc;
            unsigned fa0 = Xb[abase];
            unsigned fa1 = Xb[abase + 8 * XSTR];
            unsigned fa2 = Xb[abase + 4];
            unsigned fa3 = Xb[abase + 8 * XSTR + 4];
            int bb0 = (kt * 8 + qc) * WSTR + qr;
            int bb1 = bb0 + 4 * WSTR;
#pragma unroll
            for (int nt = 0; nt < 8; nt++)
                mma_tf32(Cf[nt][0], Cf[nt][1], Cf[nt][2], Cf[nt][3],
                         fa0, fa1, fa2, fa3, Wb[bb0 + nt * 8], Wb[bb1 + nt * 8]);
        }
        CP_WAIT0();
        __syncthreads();
    }

    const int r0 = m0 + w * 16 + qr;
#pragma unroll
    for (int nt = 0; nt < 8; nt++) {
        int n = n0 + nt * 8 + 2 * qc;
        float bv0 = bo[n], bv1 = bo[n + 1];
        *(float2*)&out[r0 * CC + n] =
            make_float2(Cf[nt][0] + bv0, Cf[nt][1] + bv1);
        *(float2*)&out[(r0 + 8) * CC + n] =
            make_float2(Cf[nt][2] + bv0, Cf[nt][3] + bv1);
    }
}

// ---------------- launcher ---------------------------------------------------
extern "C" void kernel_launch(void* const* d_in, const int* in_sizes, int n_in,
                              void* d_out, int out_size) {
    const float* x  = (const float*)d_in[0];
    const float* wq = (const float*)d_in[1];
    const float* bq = (const float*)d_in[2];
    const float* wk = (const float*)d_in[3];
    const float* bk = (const float*)d_in[4];
    const float* wv = (const float*)d_in[5];
    const float* bv = (const float*)d_in[6];
    const float* wo = (const float*)d_in[7];
    const float* bo = (const float*)d_in[8];
    float* out = (float*)d_out;

    cudaFuncSetAttribute(attn_k, cudaFuncAttributeMaxDynamicSharedMemorySize,
                         ATTN_SMEM_BYTES);
    cudaFuncSetAttribute(qkv_tc_k, cudaFuncAttributeMaxDynamicSharedMemorySize,
                         GEMM_SMEM_BYTES);
    cudaFuncSetAttribute(out_proj_tc_k,
                         cudaFuncAttributeMaxDynamicSharedMemorySize,
                         GEMM_SMEM_BYTES);

    pack_w_k<<<(CC * NQKV + 255) / 256, 256>>>(wq, wk, wv);
    pack_wo_k<<<(CC * CC + 255) / 256, 256>>>(wo);
    xconv_k<<<(BB * TT * CC + 255) / 256, 256>>>(x);
    rope_table_k<<<(TT * 32 + 255) / 256, 256>>>();
    qkv_tc_k<<<dim3(NQKV / 64, (BB * TT) / 128), 256, GEMM_SMEM_BYTES>>>(bq, bk, bv);
    attn_k<<<dim3(BB * HH, 24), 256, ATTN_SMEM_BYTES>>>();
    attn_merge_k<<<(BB * 1024 * CC + 255) / 256, 256>>>();
    out_proj_tc_k<<<dim3(CC / 64, (BB * TT) / 128), 256, GEMM_SMEM_BYTES>>>(bo, out);
}